// round 1
// baseline (speedup 1.0000x reference)
#include <cuda_runtime.h>
#include <math.h>

// ---------------- problem constants ----------------
#define KK 5
#define BB 32
#define TT 64
#define DIN 4096
#define HH 256            // GRU hidden
#define G3 768            // 3*H
#define H2 512            // 2*H
#define NSEQ 192          // 160 S-sequences + 32 Q-sequences
#define NS 160            // K*B
#define ATTN_SMEM ((64*65*3 + 64*520)*4)

// ---------------- scratch (device globals; no allocation allowed) ----------------
__device__ float g_XP[(size_t)NSEQ * TT * 1536];   // input projections, fwd|bwd gates
__device__ float g_F [(size_t)NSEQ * TT * H2];     // BiGRU features [n][t][fwd256|bwd256]
__device__ float g_keys[(size_t)NS * TT * H2];     // W_attn(F_S)+bias
__device__ float g_diff[(size_t)NS * TT * 2];      // (cos, euc) dml inputs

__device__ __forceinline__ float sigm(float x) { return 1.f / (1.f + expf(-x)); }

// ---------------- generic tiled SGEMM: C[m][g] = sum_k Arow(m)[k]*Brow(g)[k] + bias[g] ----------------
// mode 0: A = [feats_S | feats_Q], C = g_XP.   mode 1: A = g_F (first Msplit rows), C = g_keys.
__global__ void __launch_bounds__(256) gemm_bias(
    int mode,
    const float* __restrict__ A1, const float* __restrict__ A2, int Msplit,
    const float* __restrict__ B1, const float* __restrict__ B2, int Nsplit,
    const float* __restrict__ bias1, const float* __restrict__ bias2,
    int M, int N, int K)
{
    __shared__ float As[16][128];
    __shared__ float Bs[16][128];

    const float* A1p = (mode == 0) ? A1 : g_F;
    const float* A2p = (mode == 0) ? A2 : g_F;
    float* C = (mode == 0) ? g_XP : g_keys;

    int bm = blockIdx.x * 128;
    int bn = blockIdx.y * 128;
    int tid = threadIdx.x;
    int tx = tid & 15, ty = tid >> 4;

    float acc[8][8];
#pragma unroll
    for (int i = 0; i < 8; i++)
#pragma unroll
        for (int j = 0; j < 8; j++) acc[i][j] = 0.f;

    for (int k0 = 0; k0 < K; k0 += 16) {
#pragma unroll
        for (int l = 0; l < 2; l++) {
            int idx = tid + l * 256;            // float4 index in 128x16 tile
            int row = idx >> 2;
            int col = (idx & 3) * 4;
            int m = bm + row;
            const float* Ar = (m < Msplit) ? (A1p + (size_t)m * K)
                                           : (A2p + (size_t)(m - Msplit) * K);
            float4 v = *(const float4*)(Ar + k0 + col);
            As[col + 0][row] = v.x; As[col + 1][row] = v.y;
            As[col + 2][row] = v.z; As[col + 3][row] = v.w;

            int g = bn + row;
            const float* Br = (g < Nsplit) ? (B1 + (size_t)g * K)
                                           : (B2 + (size_t)(g - Nsplit) * K);
            float4 w = *(const float4*)(Br + k0 + col);
            Bs[col + 0][row] = w.x; Bs[col + 1][row] = w.y;
            Bs[col + 2][row] = w.z; Bs[col + 3][row] = w.w;
        }
        __syncthreads();
#pragma unroll
        for (int kk = 0; kk < 16; kk++) {
            float a[8], b[8];
#pragma unroll
            for (int i = 0; i < 8; i++) a[i] = As[kk][ty * 8 + i];
#pragma unroll
            for (int j = 0; j < 8; j++) b[j] = Bs[kk][tx * 8 + j];
#pragma unroll
            for (int i = 0; i < 8; i++)
#pragma unroll
                for (int j = 0; j < 8; j++) acc[i][j] += a[i] * b[j];
        }
        __syncthreads();
    }

#pragma unroll
    for (int i = 0; i < 8; i++) {
        int m = bm + ty * 8 + i;
#pragma unroll
        for (int j = 0; j < 8; j++) {
            int g = bn + tx * 8 + j;
            float bia = (g < Nsplit) ? bias1[g] : bias2[g - Nsplit];
            C[(size_t)m * N + g] = acc[i][j] + bia;
        }
    }
}

// ---------------- BiGRU recurrent scan: 64 blocks x 3 sequences, 256 threads ----------------
__global__ void __launch_bounds__(256) bigru_scan(
    const float* __restrict__ Whh_f, const float* __restrict__ bhh_f,
    const float* __restrict__ Whh_b, const float* __restrict__ bhh_b)
{
    __shared__ float sh[2][3][256];
    int tid = threadIdx.x;
    int nb = blockIdx.x * 3;

#pragma unroll
    for (int d = 0; d < 2; d++)
#pragma unroll
        for (int s = 0; s < 3; s++) sh[d][s][tid] = 0.f;
    __syncthreads();

    const float* W[2]  = { Whh_f, Whh_b };
    const float* BH[2] = { bhh_f, bhh_b };
    float bh_r[2], bh_z[2], bh_n[2];
#pragma unroll
    for (int d = 0; d < 2; d++) {
        bh_r[d] = BH[d][tid]; bh_z[d] = BH[d][256 + tid]; bh_n[d] = BH[d][512 + tid];
    }

    for (int t = 0; t < 64; t++) {
        float hn[2][3];
#pragma unroll
        for (int d = 0; d < 2; d++) {
            int tt = d ? (63 - t) : t;
            const float* wr = W[d] + (size_t)tid * 256;
            const float* wz = W[d] + (size_t)(256 + tid) * 256;
            const float* wn = W[d] + (size_t)(512 + tid) * 256;
            float ar[3] = {0,0,0}, az[3] = {0,0,0}, an[3] = {0,0,0};
            for (int i = 0; i < 256; i += 4) {
                float4 r4 = *(const float4*)(wr + i);
                float4 z4 = *(const float4*)(wz + i);
                float4 n4 = *(const float4*)(wn + i);
#pragma unroll
                for (int s = 0; s < 3; s++) {
                    float4 h4 = *(const float4*)(&sh[d][s][i]);
                    ar[s] += r4.x * h4.x; ar[s] += r4.y * h4.y; ar[s] += r4.z * h4.z; ar[s] += r4.w * h4.w;
                    az[s] += z4.x * h4.x; az[s] += z4.y * h4.y; az[s] += z4.z * h4.z; az[s] += z4.w * h4.w;
                    an[s] += n4.x * h4.x; an[s] += n4.y * h4.y; an[s] += n4.z * h4.z; an[s] += n4.w * h4.w;
                }
            }
#pragma unroll
            for (int s = 0; s < 3; s++) {
                int n = nb + s;
                const float* xp = g_XP + ((size_t)n * 64 + tt) * 1536 + d * 768;
                float r  = sigm(xp[tid]       + ar[s] + bh_r[d]);
                float z  = sigm(xp[256 + tid] + az[s] + bh_z[d]);
                float ng = tanhf(xp[512 + tid] + r * (an[s] + bh_n[d]));
                hn[d][s] = (1.f - z) * ng + z * sh[d][s][tid];
            }
        }
        __syncthreads();
#pragma unroll
        for (int d = 0; d < 2; d++) {
            int tt = d ? (63 - t) : t;
#pragma unroll
            for (int s = 0; s < 3; s++) {
                sh[d][s][tid] = hn[d][s];
                g_F[((size_t)(nb + s) * 64 + tt) * 512 + d * 256 + tid] = hn[d][s];
            }
        }
        __syncthreads();
    }
}

// ---------------- attention + softmax + Hc + cos/euc, one block per (k,b) ----------------
__global__ void __launch_bounds__(256) attn_kernel(
    const int* __restrict__ s_ln_arr, const int* __restrict__ q_ln_arr,
    float* __restrict__ d_out)
{
    extern __shared__ float sm[];
    float* ssc = sm;                 // [64][65] scores -> A
    float* sk  = sm + 64 * 65;       // [64][65] keys tile
    float* sq  = sk + 64 * 65;       // [64][65] F_Q tile
    float* shc = sq + 64 * 65;       // [64][520] Hc

    int kb = blockIdx.x;
    int b = kb & 31;
    int tid = threadIdx.x;
    int q_ln = q_ln_arr[b];
    int s_ln = s_ln_arr[kb];

    const float* keys = g_keys + (size_t)kb * 64 * 512;
    const float* FQ   = g_F + ((size_t)(160 + b) * 64) * 512;
    const float* FS   = g_F + ((size_t)kb * 64) * 512;

    // scores[s][q] = sum_g keys[s][g] * FQ[q][g]
    int tx = tid & 15, ty = tid >> 4;
    float acc[4][4];
#pragma unroll
    for (int i = 0; i < 4; i++)
#pragma unroll
        for (int j = 0; j < 4; j++) acc[i][j] = 0.f;

    for (int g0 = 0; g0 < 512; g0 += 64) {
#pragma unroll
        for (int l = 0; l < 4; l++) {
            int idx = tid + l * 256;            // float4 idx in 64x64 tile
            int row = idx >> 4;
            int col = (idx & 15) * 4;
            float4 v = *(const float4*)(keys + row * 512 + g0 + col);
            float* dk = sk + row * 65 + col;
            dk[0] = v.x; dk[1] = v.y; dk[2] = v.z; dk[3] = v.w;
            float4 w = *(const float4*)(FQ + row * 512 + g0 + col);
            float* dq = sq + row * 65 + col;
            dq[0] = w.x; dq[1] = w.y; dq[2] = w.z; dq[3] = w.w;
        }
        __syncthreads();
        for (int g = 0; g < 64; g++) {
            float a[4], bq[4];
#pragma unroll
            for (int i = 0; i < 4; i++) a[i]  = sk[(ty * 4 + i) * 65 + g];
#pragma unroll
            for (int j = 0; j < 4; j++) bq[j] = sq[(tx * 4 + j) * 65 + g];
#pragma unroll
            for (int i = 0; i < 4; i++)
#pragma unroll
                for (int j = 0; j < 4; j++) acc[i][j] += a[i] * bq[j];
        }
        __syncthreads();
    }
#pragma unroll
    for (int i = 0; i < 4; i++)
#pragma unroll
        for (int j = 0; j < 4; j++) {
            int s = ty * 4 + i, q = tx * 4 + j;
            ssc[s * 65 + q] = (q < q_ln) ? acc[i][j] : -INFINITY;
        }
    __syncthreads();

    // softmax over q per s-row (8 warps x 8 rows), zero invalid s rows
    int warp = tid >> 5, lane = tid & 31;
    for (int si = 0; si < 8; si++) {
        int s = warp * 8 + si;
        float v0 = ssc[s * 65 + lane];
        float v1 = ssc[s * 65 + 32 + lane];
        float mx = fmaxf(v0, v1);
#pragma unroll
        for (int o = 16; o > 0; o >>= 1) mx = fmaxf(mx, __shfl_xor_sync(~0u, mx, o));
        float e0 = expf(v0 - mx), e1 = expf(v1 - mx);
        float su = e0 + e1;
#pragma unroll
        for (int o = 16; o > 0; o >>= 1) su += __shfl_xor_sync(~0u, su, o);
        float sc = (s < s_ln) ? (1.f / su) : 0.f;
        ssc[s * 65 + lane] = e0 * sc;
        ssc[s * 65 + 32 + lane] = e1 * sc;
    }
    __syncthreads();

    if (kb == NS - 1) {           // last (class, sample) pair -> output A [64,64]
        for (int i = tid; i < 4096; i += 256)
            d_out[i] = ssc[(i >> 6) * 65 + (i & 63)];
    }

    // Hc[q][h] = sum_s A[s][q] * FS[s][h]; 2 passes x (4 q-grp x 8q) x (64 thr x 8h)
    int hcol = tid & 63;
    int qgrp = tid >> 6;
#pragma unroll
    for (int pass = 0; pass < 2; pass++) {
        int qb = qgrp * 8 + pass * 32;
        float hc[8][8];
#pragma unroll
        for (int qi = 0; qi < 8; qi++)
#pragma unroll
            for (int hj = 0; hj < 8; hj++) hc[qi][hj] = 0.f;
        for (int s = 0; s < 64; s++) {
            float4 f0 = *(const float4*)(FS + s * 512 + hcol * 8);
            float4 f1 = *(const float4*)(FS + s * 512 + hcol * 8 + 4);
#pragma unroll
            for (int qi = 0; qi < 8; qi++) {
                float a = ssc[s * 65 + qb + qi];
                hc[qi][0] += a * f0.x; hc[qi][1] += a * f0.y;
                hc[qi][2] += a * f0.z; hc[qi][3] += a * f0.w;
                hc[qi][4] += a * f1.x; hc[qi][5] += a * f1.y;
                hc[qi][6] += a * f1.z; hc[qi][7] += a * f1.w;
            }
        }
#pragma unroll
        for (int qi = 0; qi < 8; qi++) {
            float* dst = shc + (qb + qi) * 520 + hcol * 8;
#pragma unroll
            for (int hj = 0; hj < 8; hj++) dst[hj] = hc[qi][hj];
        }
    }
    __syncthreads();

    // per-q reductions: dot(q,Hc), |q|^2, |Hc|^2, |q-Hc|^2
    for (int qi = 0; qi < 8; qi++) {
        int q = warp + qi * 8;
        float dot = 0.f, nq = 0.f, nh = 0.f, ee = 0.f;
        for (int c = 0; c < 16; c++) {
            int h = lane + c * 32;
            float fq = FQ[q * 512 + h];
            float hv = shc[q * 520 + h];
            dot += fq * hv; nq += fq * fq; nh += hv * hv;
            float dd = fq - hv; ee += dd * dd;
        }
#pragma unroll
        for (int o = 16; o > 0; o >>= 1) {
            dot += __shfl_xor_sync(~0u, dot, o);
            nq  += __shfl_xor_sync(~0u, nq,  o);
            nh  += __shfl_xor_sync(~0u, nh,  o);
            ee  += __shfl_xor_sync(~0u, ee,  o);
        }
        if (lane == 0) {
            float cosv = dot / fmaxf(sqrtf(nq) * sqrtf(nh), 1e-6f);
            float eucv = sqrtf(ee);
            float msk = (q < q_ln) ? 1.f : 0.f;
            g_diff[((size_t)kb * 64 + q) * 2 + 0] = cosv * msk;
            g_diff[((size_t)kb * 64 + q) * 2 + 1] = eucv * msk;
        }
    }
}

// ---------------- dml GRU over diff + FC head: 54 blocks x 3 sequences ----------------
__global__ void __launch_bounds__(256) dml_kernel(
    const float* __restrict__ Wih, const float* __restrict__ Whh,
    const float* __restrict__ bih, const float* __restrict__ bhh,
    const float* __restrict__ fcW, const float* __restrict__ fcb,
    float* __restrict__ d_out)
{
    __shared__ float sh[3][256];
    __shared__ float red[256];
    int tid = threadIdx.x;
    int nb = blockIdx.x * 3;

#pragma unroll
    for (int s = 0; s < 3; s++) sh[s][tid] = 0.f;
    __syncthreads();

    float wi_r0 = Wih[tid * 2],         wi_r1 = Wih[tid * 2 + 1];
    float wi_z0 = Wih[(256 + tid) * 2], wi_z1 = Wih[(256 + tid) * 2 + 1];
    float wi_n0 = Wih[(512 + tid) * 2], wi_n1 = Wih[(512 + tid) * 2 + 1];
    float bi_r = bih[tid], bi_z = bih[256 + tid], bi_n = bih[512 + tid];
    float bh_r = bhh[tid], bh_z = bhh[256 + tid], bh_n = bhh[512 + tid];
    const float* wr = Whh + (size_t)tid * 256;
    const float* wz = Whh + (size_t)(256 + tid) * 256;
    const float* wn = Whh + (size_t)(512 + tid) * 256;

    for (int t = 0; t < 64; t++) {
        float ar[3] = {0,0,0}, az[3] = {0,0,0}, an[3] = {0,0,0};
        for (int i = 0; i < 256; i += 4) {
            float4 r4 = *(const float4*)(wr + i);
            float4 z4 = *(const float4*)(wz + i);
            float4 n4 = *(const float4*)(wn + i);
#pragma unroll
            for (int s = 0; s < 3; s++) {
                float4 h4 = *(const float4*)(&sh[s][i]);
                ar[s] += r4.x * h4.x; ar[s] += r4.y * h4.y; ar[s] += r4.z * h4.z; ar[s] += r4.w * h4.w;
                az[s] += z4.x * h4.x; az[s] += z4.y * h4.y; az[s] += z4.z * h4.z; az[s] += z4.w * h4.w;
                an[s] += n4.x * h4.x; an[s] += n4.y * h4.y; an[s] += n4.z * h4.z; an[s] += n4.w * h4.w;
            }
        }
        float hn[3];
#pragma unroll
        for (int s = 0; s < 3; s++) {
            int n = nb + s;
            float d0 = 0.f, d1 = 0.f;
            if (n < NS) {
                d0 = g_diff[((size_t)n * 64 + t) * 2 + 0];
                d1 = g_diff[((size_t)n * 64 + t) * 2 + 1];
            }
            float xr = wi_r0 * d0 + wi_r1 * d1 + bi_r;
            float xz = wi_z0 * d0 + wi_z1 * d1 + bi_z;
            float xn = wi_n0 * d0 + wi_n1 * d1 + bi_n;
            float r  = sigm(xr + ar[s] + bh_r);
            float z  = sigm(xz + az[s] + bh_z);
            float ng = tanhf(xn + r * (an[s] + bh_n));
            hn[s] = (1.f - z) * ng + z * sh[s][tid];
        }
        __syncthreads();
#pragma unroll
        for (int s = 0; s < 3; s++) sh[s][tid] = hn[s];
        __syncthreads();
    }

    float fw = fcW[tid];
    for (int s = 0; s < 3; s++) {
        int n = nb + s;
        red[tid] = fw * sh[s][tid];
        __syncthreads();
        for (int off = 128; off > 0; off >>= 1) {
            if (tid < off) red[tid] += red[tid + off];
            __syncthreads();
        }
        if (tid == 0 && n < NS)
            d_out[4096 + n] = sigm(red[0] + fcb[0]);
        __syncthreads();
    }
}

// ---------------- launcher ----------------
extern "C" void kernel_launch(void* const* d_in, const int* in_sizes, int n_in,
                              void* d_out, int out_size)
{
    const float* feats_S  = (const float*)d_in[0];
    const float* feats_Q  = (const float*)d_in[1];
    const float* Wih_f    = (const float*)d_in[2];
    const float* Whh_f    = (const float*)d_in[3];
    const float* bih_f    = (const float*)d_in[4];
    const float* bhh_f    = (const float*)d_in[5];
    const float* Wih_b    = (const float*)d_in[6];
    const float* Whh_b    = (const float*)d_in[7];
    const float* bih_b    = (const float*)d_in[8];
    const float* bhh_b    = (const float*)d_in[9];
    const float* W_attn   = (const float*)d_in[10];
    const float* attn_b   = (const float*)d_in[11];
    const float* dml_Wih  = (const float*)d_in[12];
    const float* dml_Whh  = (const float*)d_in[13];
    const float* dml_bih  = (const float*)d_in[14];
    const float* dml_bhh  = (const float*)d_in[15];
    const float* fc_W     = (const float*)d_in[16];
    const float* fc_b     = (const float*)d_in[17];
    const int*   s_ln     = (const int*)d_in[18];
    const int*   q_ln     = (const int*)d_in[19];
    float* out = (float*)d_out;

    // 1) all input projections (S fwd+bwd, Q fwd+bwd) in one GEMM: [12288,4096] x [4096,1536]
    gemm_bias<<<dim3(96, 12), 256>>>(0, feats_S, feats_Q, 10240,
                                     Wih_f, Wih_b, 768, bih_f, bih_b,
                                     12288, 1536, 4096);
    // 2) bidirectional GRU recurrence over all 192 sequences
    bigru_scan<<<64, 256>>>(Whh_f, bhh_f, Whh_b, bhh_b);
    // 3) keys = W_attn(F_S) + bias : [10240,512] x [512,512]
    gemm_bias<<<dim3(80, 4), 256>>>(1, nullptr, nullptr, 10240,
                                    W_attn, W_attn, 512, attn_b, attn_b,
                                    10240, 512, 512);
    // 4) scores -> softmax -> A -> Hc -> (cos,euc); emits A[-1,-1] to out[0:4096]
    cudaFuncSetAttribute(attn_kernel, cudaFuncAttributeMaxDynamicSharedMemorySize, ATTN_SMEM);
    attn_kernel<<<160, 256, ATTN_SMEM>>>(s_ln, q_ln, out);
    // 5) dml GRU over (cos,euc) + sigmoid(FC) -> out[4096:4256]
    dml_kernel<<<54, 256>>>(dml_Wih, dml_Whh, dml_bih, dml_bhh, fc_W, fc_b, out);
}

// round 3
// speedup vs baseline: 1.3675x; 1.3675x over previous
#include <cuda_runtime.h>
#include <cuda_bf16.h>
#include <math.h>
#include <stdint.h>

// ---------------- problem constants ----------------
#define KK 5
#define BB 32
#define TT 64
#define DIN 4096
#define HH 256            // GRU hidden
#define H2 512            // 2*H
#define NSEQ 192          // 160 S-sequences + 32 Q-sequences
#define NS 160            // K*B
#define MTOT 12288        // NSEQ*TT rows
#define NTOT 1536         // 3H fwd | 3H bwd
#define ATTN_SMEM ((64*65*3 + 64*520)*4)

#define AELEMS ((size_t)MTOT * DIN)
#define BELEMS ((size_t)NTOT * DIN)

// mma-GEMM tiling
#define BKC 32
#define NCHUNK (DIN / BKC)      // 128
#define PADROW 40               // bf16 elems per smem row (32 + 8 pad) = 80 bytes
#define PLANE_B (128 * PADROW * 2)   // 10240 bytes per plane tile
#define STAGE_B (4 * PLANE_B)        // Ah, Al, Bh, Bl = 40960 bytes
#define STAGES 3
#define GMM_SMEM (STAGES * STAGE_B)  // 122880

// ---------------- scratch (device globals; no allocation allowed) ----------------
__device__ float g_XP[(size_t)NSEQ * TT * NTOT];   // input projections, fwd|bwd gates
__device__ float g_F [(size_t)NSEQ * TT * H2];     // BiGRU features [n][t][fwd256|bwd256]
__device__ float g_keys[(size_t)NS * TT * H2];     // W_attn(F_S)+bias
__device__ float g_diff[(size_t)NS * TT * 2];      // (cos, euc) dml inputs
__device__ __nv_bfloat16 g_Abf[2 * AELEMS];        // bf16 hi|lo planes of inputs
__device__ __nv_bfloat16 g_Bbf[2 * BELEMS];        // bf16 hi|lo planes of Wih_f|Wih_b

__device__ __forceinline__ float sigm(float x) { return 1.f / (1.f + expf(-x)); }

__device__ __forceinline__ uint32_t smem_u32(const void* p) {
    uint32_t a;
    asm("{ .reg .u64 t; cvta.to.shared.u64 t, %1; cvt.u32.u64 %0, t; }" : "=r"(a) : "l"(p));
    return a;
}
__device__ __forceinline__ void ldsm4(uint32_t* r, uint32_t a) {
    asm volatile("ldmatrix.sync.aligned.m8n8.x4.shared.b16 {%0,%1,%2,%3}, [%4];"
        : "=r"(r[0]), "=r"(r[1]), "=r"(r[2]), "=r"(r[3]) : "r"(a));
}
__device__ __forceinline__ void mma_bf16(float* c, const uint32_t* a, uint32_t b0, uint32_t b1) {
    asm volatile("mma.sync.aligned.m16n8k16.row.col.f32.bf16.bf16.f32 "
        "{%0,%1,%2,%3}, {%4,%5,%6,%7}, {%8,%9}, {%0,%1,%2,%3};"
        : "+f"(c[0]), "+f"(c[1]), "+f"(c[2]), "+f"(c[3])
        : "r"(a[0]), "r"(a[1]), "r"(a[2]), "r"(a[3]), "r"(b0), "r"(b1));
}
__device__ __forceinline__ void cpasync16(uint32_t s, const void* g) {
    asm volatile("cp.async.cg.shared.global [%0], [%1], 16;" :: "r"(s), "l"(g));
}
#define CP_COMMIT() asm volatile("cp.async.commit_group;" ::: "memory")

// packed f32x2 fma (compile-verified on sm_103 in R1)
__device__ __forceinline__ void ffma2(uint64_t& acc, uint64_t a, uint64_t b) {
    asm("fma.rn.f32x2 %0, %1, %2, %0;" : "+l"(acc) : "l"(a), "l"(b));
}
__device__ __forceinline__ float upk_sum(uint64_t v) {
    float x, y;
    asm("mov.b64 {%0,%1}, %2;" : "=f"(x), "=f"(y) : "l"(v));
    return x + y;
}

// ---------------- fp32 -> bf16 hi/lo split ----------------
__global__ void __launch_bounds__(256) convert_split(
    const float* __restrict__ src, __nv_bfloat16* __restrict__ hi, __nv_bfloat16* __restrict__ lo)
{
    size_t i = ((size_t)blockIdx.x * 256 + threadIdx.x) * 4;
    float4 v = *(const float4*)(src + i);
    float vv[4] = { v.x, v.y, v.z, v.w };
    union { __nv_bfloat16 b[4]; uint2 u; } H, L;
#pragma unroll
    for (int j = 0; j < 4; j++) {
        H.b[j] = __float2bfloat16(vv[j]);
        L.b[j] = __float2bfloat16(vv[j] - __bfloat162float(H.b[j]));
    }
    *(uint2*)(hi + i) = H.u;
    *(uint2*)(lo + i) = L.u;
}

// ---------------- bf16-split GEMM via mma.sync: g_XP = X @ W^T + bias ----------------
// grid (12 N-tiles fastest, 96 M-tiles), 256 threads, tile 128x128, K-chunk 32, 3 stages.
__global__ void __launch_bounds__(256) gemm_mma(
    const float* __restrict__ bias1, const float* __restrict__ bias2)
{
    extern __shared__ __align__(128) char smem[];
    uint32_t sbase = smem_u32(smem);
    int tid = threadIdx.x;
    int wid = tid >> 5, lane = tid & 31;
    int warp_m = wid & 1, warp_n = wid >> 1;
    int bn = blockIdx.x * 128, bm = blockIdx.y * 128;

    float acc[4][4][4];
#pragma unroll
    for (int i = 0; i < 4; i++)
#pragma unroll
        for (int j = 0; j < 4; j++)
#pragma unroll
            for (int c = 0; c < 4; c++) acc[i][j][c] = 0.f;

    auto load_stage = [&](int ci, int s) {
        int k0 = ci * BKC;
        uint32_t sb_s = sbase + s * STAGE_B;
#pragma unroll
        for (int l = 0; l < 8; l++) {
            int chunk = tid + l * 256;
            int p = chunk >> 9;           // 0:Ah 1:Al 2:Bh 3:Bl (uniform per l)
            int r = (chunk >> 2) & 127;
            int seg = chunk & 3;
            uint32_t sa = sb_s + p * PLANE_B + r * 80 + seg * 16;
            const __nv_bfloat16* gp;
            if (p < 2)
                gp = g_Abf + (size_t)p * AELEMS + (size_t)(bm + r) * DIN + k0 + seg * 8;
            else
                gp = g_Bbf + (size_t)(p - 2) * BELEMS + (size_t)(bn + r) * DIN + k0 + seg * 8;
            cpasync16(sa, gp);
        }
        CP_COMMIT();
    };

    auto compute_stage = [&](int s) {
        uint32_t base = sbase + s * STAGE_B;
#pragma unroll
        for (int kh = 0; kh < 2; kh++) {
            uint32_t ah[16], al[16], bh[8], bl[8];
#pragma unroll
            for (int mf = 0; mf < 4; mf++) {
                int row = warp_m * 64 + mf * 16 + (lane & 7) + ((lane >> 3) & 1) * 8;
                uint32_t ad = base + row * 80 + kh * 32 + ((lane >> 4) & 1) * 16;
                ldsm4(&ah[mf * 4], ad);
                ldsm4(&al[mf * 4], ad + PLANE_B);
            }
#pragma unroll
            for (int nf2 = 0; nf2 < 2; nf2++) {
                int row = warp_n * 32 + nf2 * 16 + ((lane >> 4) & 1) * 8 + (lane & 7);
                uint32_t bd = base + 2 * PLANE_B + row * 80 + kh * 32 + ((lane >> 3) & 1) * 16;
                ldsm4(&bh[nf2 * 4], bd);
                ldsm4(&bl[nf2 * 4], bd + PLANE_B);
            }
#pragma unroll
            for (int mf = 0; mf < 4; mf++)
#pragma unroll
                for (int nf = 0; nf < 4; nf++) {
                    int bi = (nf >> 1) * 4 + (nf & 1) * 2;
                    mma_bf16(acc[mf][nf], &ah[mf * 4], bh[bi], bh[bi + 1]);
                    mma_bf16(acc[mf][nf], &ah[mf * 4], bl[bi], bl[bi + 1]);
                    mma_bf16(acc[mf][nf], &al[mf * 4], bh[bi], bh[bi + 1]);
                }
        }
    };

    load_stage(0, 0);
    load_stage(1, 1);

#pragma unroll 1
    for (int ci = 0; ci < NCHUNK; ci++) {
        if (ci < NCHUNK - 1) asm volatile("cp.async.wait_group 1;" ::: "memory");
        else                 asm volatile("cp.async.wait_group 0;" ::: "memory");
        __syncthreads();
        if (ci + 2 < NCHUNK) load_stage(ci + 2, (ci + 2) % STAGES);
        compute_stage(ci % STAGES);
    }

    // epilogue: add bias, write fp32
    float bcol[4][2];
#pragma unroll
    for (int nf = 0; nf < 4; nf++) {
        int col = bn + warp_n * 32 + nf * 8 + (lane & 3) * 2;
        bcol[nf][0] = (col < 768) ? bias1[col] : bias2[col - 768];
        bcol[nf][1] = (col + 1 < 768) ? bias1[col + 1] : bias2[col + 1 - 768];
    }
#pragma unroll
    for (int mf = 0; mf < 4; mf++) {
        int m = bm + warp_m * 64 + mf * 16 + (lane >> 2);
#pragma unroll
        for (int nf = 0; nf < 4; nf++) {
            size_t o = (size_t)m * NTOT + bn + warp_n * 32 + nf * 8 + (lane & 3) * 2;
            float2 v0 = { acc[mf][nf][0] + bcol[nf][0], acc[mf][nf][1] + bcol[nf][1] };
            *(float2*)(g_XP + o) = v0;
            float2 v1 = { acc[mf][nf][2] + bcol[nf][0], acc[mf][nf][3] + bcol[nf][1] };
            *(float2*)(g_XP + o + (size_t)8 * NTOT) = v1;
        }
    }
}

// ---------------- fp32 tiled GEMM for keys: C[m][g] = F[m]·W_attn[g] + bias ----------------
__global__ void __launch_bounds__(256) gemm_keys(
    const float* __restrict__ B1, const float* __restrict__ bias1, int M, int N, int K)
{
    __shared__ float As[16][128];
    __shared__ float Bs[16][128];
    float* C = g_keys;
    int bm = blockIdx.x * 128, bn = blockIdx.y * 128;
    int tid = threadIdx.x;
    int tx = tid & 15, ty = tid >> 4;
    float acc[8][8];
#pragma unroll
    for (int i = 0; i < 8; i++)
#pragma unroll
        for (int j = 0; j < 8; j++) acc[i][j] = 0.f;

    for (int k0 = 0; k0 < K; k0 += 16) {
#pragma unroll
        for (int l = 0; l < 2; l++) {
            int idx = tid + l * 256;
            int row = idx >> 2;
            int col = (idx & 3) * 4;
            float4 v = *(const float4*)(g_F + (size_t)(bm + row) * K + k0 + col);
            As[col + 0][row] = v.x; As[col + 1][row] = v.y;
            As[col + 2][row] = v.z; As[col + 3][row] = v.w;
            float4 w = *(const float4*)(B1 + (size_t)(bn + row) * K + k0 + col);
            Bs[col + 0][row] = w.x; Bs[col + 1][row] = w.y;
            Bs[col + 2][row] = w.z; Bs[col + 3][row] = w.w;
        }
        __syncthreads();
#pragma unroll
        for (int kk = 0; kk < 16; kk++) {
            float a[8], b[8];
#pragma unroll
            for (int i = 0; i < 8; i++) a[i] = As[kk][ty * 8 + i];
#pragma unroll
            for (int j = 0; j < 8; j++) b[j] = Bs[kk][tx * 8 + j];
#pragma unroll
            for (int i = 0; i < 8; i++)
#pragma unroll
                for (int j = 0; j < 8; j++) acc[i][j] += a[i] * b[j];
        }
        __syncthreads();
    }
#pragma unroll
    for (int i = 0; i < 8; i++) {
        int m = bm + ty * 8 + i;
#pragma unroll
        for (int j = 0; j < 8; j++) {
            int g = bn + tx * 8 + j;
            C[(size_t)m * N + g] = acc[i][j] + bias1[g];
        }
    }
}

// ---------------- BiGRU recurrent scan: 48 blocks x 4 sequences, 256 threads ----------------
__global__ void __launch_bounds__(256) bigru_scan(
    const float* __restrict__ Whh_f, const float* __restrict__ bhh_f,
    const float* __restrict__ Whh_b, const float* __restrict__ bhh_b)
{
    __shared__ __align__(16) float sh[2][4][256];
    int tid = threadIdx.x;
    int nb = blockIdx.x * 4;

#pragma unroll
    for (int d = 0; d < 2; d++)
#pragma unroll
        for (int s = 0; s < 4; s++) sh[d][s][tid] = 0.f;
    __syncthreads();

    const float* W[2]  = { Whh_f, Whh_b };
    const float* BH[2] = { bhh_f, bhh_b };
    float bh_r[2], bh_z[2], bh_n[2];
#pragma unroll
    for (int d = 0; d < 2; d++) {
        bh_r[d] = BH[d][tid]; bh_z[d] = BH[d][256 + tid]; bh_n[d] = BH[d][512 + tid];
    }

    for (int t = 0; t < 64; t++) {
        float hn[2][4];
#pragma unroll
        for (int d = 0; d < 2; d++) {
            int tt = d ? (63 - t) : t;
            const float* wr = W[d] + (size_t)tid * 256;
            const float* wz = W[d] + (size_t)(256 + tid) * 256;
            const float* wn = W[d] + (size_t)(512 + tid) * 256;
            uint64_t ar[4] = {0,0,0,0}, az[4] = {0,0,0,0}, an[4] = {0,0,0,0};
            for (int i = 0; i < 256; i += 4) {
                ulonglong2 r2 = *(const ulonglong2*)(wr + i);
                ulonglong2 z2 = *(const ulonglong2*)(wz + i);
                ulonglong2 n2 = *(const ulonglong2*)(wn + i);
#pragma unroll
                for (int s = 0; s < 4; s++) {
                    ulonglong2 h2 = *(const ulonglong2*)(&sh[d][s][i]);
                    ffma2(ar[s], r2.x, h2.x); ffma2(ar[s], r2.y, h2.y);
                    ffma2(az[s], z2.x, h2.x); ffma2(az[s], z2.y, h2.y);
                    ffma2(an[s], n2.x, h2.x); ffma2(an[s], n2.y, h2.y);
                }
            }
#pragma unroll
            for (int s = 0; s < 4; s++) {
                int n = nb + s;
                const float* xp = g_XP + ((size_t)n * 64 + tt) * NTOT + d * 768;
                float r  = sigm(xp[tid]       + upk_sum(ar[s]) + bh_r[d]);
                float z  = sigm(xp[256 + tid] + upk_sum(az[s]) + bh_z[d]);
                float ng = tanhf(xp[512 + tid] + r * (upk_sum(an[s]) + bh_n[d]));
                hn[d][s] = (1.f - z) * ng + z * sh[d][s][tid];
            }
        }
        __syncthreads();
#pragma unroll
        for (int d = 0; d < 2; d++) {
            int tt = d ? (63 - t) : t;
#pragma unroll
            for (int s = 0; s < 4; s++) {
                sh[d][s][tid] = hn[d][s];
                g_F[((size_t)(nb + s) * 64 + tt) * 512 + d * 256 + tid] = hn[d][s];
            }
        }
        __syncthreads();
    }
}

// ---------------- attention + softmax + Hc + cos/euc, one block per (k,b) ----------------
__global__ void __launch_bounds__(256) attn_kernel(
    const int* __restrict__ s_ln_arr, const int* __restrict__ q_ln_arr,
    float* __restrict__ d_out)
{
    extern __shared__ float sm[];
    float* ssc = sm;                 // [64][65] scores -> A
    float* sk  = sm + 64 * 65;       // [64][65] keys tile
    float* sq  = sk + 64 * 65;       // [64][65] F_Q tile
    float* shc = sq + 64 * 65;       // [64][520] Hc

    int kb = blockIdx.x;
    int b = kb & 31;
    int tid = threadIdx.x;
    int q_ln = q_ln_arr[b];
    int s_ln = s_ln_arr[kb];

    const float* keys = g_keys + (size_t)kb * 64 * 512;
    const float* FQ   = g_F + ((size_t)(160 + b) * 64) * 512;
    const float* FS   = g_F + ((size_t)kb * 64) * 512;

    int tx = tid & 15, ty = tid >> 4;
    float acc[4][4];
#pragma unroll
    for (int i = 0; i < 4; i++)
#pragma unroll
        for (int j = 0; j < 4; j++) acc[i][j] = 0.f;

    for (int g0 = 0; g0 < 512; g0 += 64) {
#pragma unroll
        for (int l = 0; l < 4; l++) {
            int idx = tid + l * 256;
            int row = idx >> 4;
            int col = (idx & 15) * 4;
            float4 v = *(const float4*)(keys + row * 512 + g0 + col);
            float* dk = sk + row * 65 + col;
            dk[0] = v.x; dk[1] = v.y; dk[2] = v.z; dk[3] = v.w;
            float4 w = *(const float4*)(FQ + row * 512 + g0 + col);
            float* dq = sq + row * 65 + col;
            dq[0] = w.x; dq[1] = w.y; dq[2] = w.z; dq[3] = w.w;
        }
        __syncthreads();
        for (int g = 0; g < 64; g++) {
            float a[4], bq[4];
#pragma unroll
            for (int i = 0; i < 4; i++) a[i]  = sk[(ty * 4 + i) * 65 + g];
#pragma unroll
            for (int j = 0; j < 4; j++) bq[j] = sq[(tx * 4 + j) * 65 + g];
#pragma unroll
            for (int i = 0; i < 4; i++)
#pragma unroll
                for (int j = 0; j < 4; j++) acc[i][j] += a[i] * bq[j];
        }
        __syncthreads();
    }
#pragma unroll
    for (int i = 0; i < 4; i++)
#pragma unroll
        for (int j = 0; j < 4; j++) {
            int s = ty * 4 + i, q = tx * 4 + j;
            ssc[s * 65 + q] = (q < q_ln) ? acc[i][j] : -INFINITY;
        }
    __syncthreads();

    int warp = tid >> 5, lane = tid & 31;
    for (int si = 0; si < 8; si++) {
        int s = warp * 8 + si;
        float v0 = ssc[s * 65 + lane];
        float v1 = ssc[s * 65 + 32 + lane];
        float mx = fmaxf(v0, v1);
#pragma unroll
        for (int o = 16; o > 0; o >>= 1) mx = fmaxf(mx, __shfl_xor_sync(~0u, mx, o));
        float e0 = expf(v0 - mx), e1 = expf(v1 - mx);
        float su = e0 + e1;
#pragma unroll
        for (int o = 16; o > 0; o >>= 1) su += __shfl_xor_sync(~0u, su, o);
        float sc = (s < s_ln) ? (1.f / su) : 0.f;
        ssc[s * 65 + lane] = e0 * sc;
        ssc[s * 65 + 32 + lane] = e1 * sc;
    }
    __syncthreads();

    if (kb == NS - 1) {
        for (int i = tid; i < 4096; i += 256)
            d_out[i] = ssc[(i >> 6) * 65 + (i & 63)];
    }

    int hcol = tid & 63;
    int qgrp = tid >> 6;
#pragma unroll
    for (int pass = 0; pass < 2; pass++) {
        int qb = qgrp * 8 + pass * 32;
        float hc[8][8];
#pragma unroll
        for (int qi = 0; qi < 8; qi++)
#pragma unroll
            for (int hj = 0; hj < 8; hj++) hc[qi][hj] = 0.f;
        for (int s = 0; s < 64; s++) {
            float4 f0 = *(const float4*)(FS + s * 512 + hcol * 8);
            float4 f1 = *(const float4*)(FS + s * 512 + hcol * 8 + 4);
#pragma unroll
            for (int qi = 0; qi < 8; qi++) {
                float a = ssc[s * 65 + qb + qi];
                hc[qi][0] += a * f0.x; hc[qi][1] += a * f0.y;
                hc[qi][2] += a * f0.z; hc[qi][3] += a * f0.w;
                hc[qi][4] += a * f1.x; hc[qi][5] += a * f1.y;
                hc[qi][6] += a * f1.z; hc[qi][7] += a * f1.w;
            }
        }
#pragma unroll
        for (int qi = 0; qi < 8; qi++) {
            float* dst = shc + (qb + qi) * 520 + hcol * 8;
#pragma unroll
            for (int hj = 0; hj < 8; hj++) dst[hj] = hc[qi][hj];
        }
    }
    __syncthreads();

    for (int qi = 0; qi < 8; qi++) {
        int q = warp + qi * 8;
        float dot = 0.f, nq = 0.f, nh = 0.f, ee = 0.f;
        for (int c = 0; c < 16; c++) {
            int h = lane + c * 32;
            float fq = FQ[q * 512 + h];
            float hv = shc[q * 520 + h];
            dot += fq * hv; nq += fq * fq; nh += hv * hv;
            float dd = fq - hv; ee += dd * dd;
        }
#pragma unroll
        for (int o = 16; o > 0; o >>= 1) {
            dot += __shfl_xor_sync(~0u, dot, o);
            nq  += __shfl_xor_sync(~0u, nq,  o);
            nh  += __shfl_xor_sync(~0u, nh,  o);
            ee  += __shfl_xor_sync(~0u, ee,  o);
        }
        if (lane == 0) {
            float cosv = dot / fmaxf(sqrtf(nq) * sqrtf(nh), 1e-6f);
            float eucv = sqrtf(ee);
            float msk = (q < q_ln) ? 1.f : 0.f;
            g_diff[((size_t)kb * 64 + q) * 2 + 0] = cosv * msk;
            g_diff[((size_t)kb * 64 + q) * 2 + 1] = eucv * msk;
        }
    }
}

// ---------------- dml GRU over diff + FC head: 40 blocks x 4 sequences ----------------
__global__ void __launch_bounds__(256) dml_kernel(
    const float* __restrict__ Wih, const float* __restrict__ Whh,
    const float* __restrict__ bih, const float* __restrict__ bhh,
    const float* __restrict__ fcW, const float* __restrict__ fcb,
    float* __restrict__ d_out)
{
    __shared__ __align__(16) float sh[4][256];
    __shared__ float red[256];
    int tid = threadIdx.x;
    int nb = blockIdx.x * 4;

#pragma unroll
    for (int s = 0; s < 4; s++) sh[s][tid] = 0.f;
    __syncthreads();

    float wi_r0 = Wih[tid * 2],         wi_r1 = Wih[tid * 2 + 1];
    float wi_z0 = Wih[(256 + tid) * 2], wi_z1 = Wih[(256 + tid) * 2 + 1];
    float wi_n0 = Wih[(512 + tid) * 2], wi_n1 = Wih[(512 + tid) * 2 + 1];
    float bi_r = bih[tid], bi_z = bih[256 + tid], bi_n = bih[512 + tid];
    float bh_r = bhh[tid], bh_z = bhh[256 + tid], bh_n = bhh[512 + tid];
    const float* wr = Whh + (size_t)tid * 256;
    const float* wz = Whh + (size_t)(256 + tid) * 256;
    const float* wn = Whh + (size_t)(512 + tid) * 256;

    for (int t = 0; t < 64; t++) {
        uint64_t ar[4] = {0,0,0,0}, az[4] = {0,0,0,0}, an[4] = {0,0,0,0};
        for (int i = 0; i < 256; i += 4) {
            ulonglong2 r2 = *(const ulonglong2*)(wr + i);
            ulonglong2 z2 = *(const ulonglong2*)(wz + i);
            ulonglong2 n2 = *(const ulonglong2*)(wn + i);
#pragma unroll
            for (int s = 0; s < 4; s++) {
                ulonglong2 h2 = *(const ulonglong2*)(&sh[s][i]);
                ffma2(ar[s], r2.x, h2.x); ffma2(ar[s], r2.y, h2.y);
                ffma2(az[s], z2.x, h2.x); ffma2(az[s], z2.y, h2.y);
                ffma2(an[s], n2.x, h2.x); ffma2(an[s], n2.y, h2.y);
            }
        }
        float hn[4];
#pragma unroll
        for (int s = 0; s < 4; s++) {
            int n = nb + s;
            float d0 = g_diff[((size_t)n * 64 + t) * 2 + 0];
            float d1 = g_diff[((size_t)n * 64 + t) * 2 + 1];
            float xr = wi_r0 * d0 + wi_r1 * d1 + bi_r;
            float xz = wi_z0 * d0 + wi_z1 * d1 + bi_z;
            float xn = wi_n0 * d0 + wi_n1 * d1 + bi_n;
            float r  = sigm(xr + upk_sum(ar[s]) + bh_r);
            float z  = sigm(xz + upk_sum(az[s]) + bh_z);
            float ng = tanhf(xn + r * (upk_sum(an[s]) + bh_n));
            hn[s] = (1.f - z) * ng + z * sh[s][tid];
        }
        __syncthreads();
#pragma unroll
        for (int s = 0; s < 4; s++) sh[s][tid] = hn[s];
        __syncthreads();
    }

    float fw = fcW[tid];
    for (int s = 0; s < 4; s++) {
        int n = nb + s;
        red[tid] = fw * sh[s][tid];
        __syncthreads();
        for (int off = 128; off > 0; off >>= 1) {
            if (tid < off) red[tid] += red[tid + off];
            __syncthreads();
        }
        if (tid == 0)
            d_out[4096 + n] = sigm(red[0] + fcb[0]);
        __syncthreads();
    }
}

// ---------------- launcher ----------------
extern "C" void kernel_launch(void* const* d_in, const int* in_sizes, int n_in,
                              void* d_out, int out_size)
{
    const float* feats_S  = (const float*)d_in[0];
    const float* feats_Q  = (const float*)d_in[1];
    const float* Wih_f    = (const float*)d_in[2];
    const float* Whh_f    = (const float*)d_in[3];
    const float* bih_f    = (const float*)d_in[4];
    const float* bhh_f    = (const float*)d_in[5];
    const float* Wih_b    = (const float*)d_in[6];
    const float* Whh_b    = (const float*)d_in[7];
    const float* bih_b    = (const float*)d_in[8];
    const float* bhh_b    = (const float*)d_in[9];
    const float* W_attn   = (const float*)d_in[10];
    const float* attn_b   = (const float*)d_in[11];
    const float* dml_Wih  = (const float*)d_in[12];
    const float* dml_Whh  = (const float*)d_in[13];
    const float* dml_bih  = (const float*)d_in[14];
    const float* dml_bhh  = (const float*)d_in[15];
    const float* fc_W     = (const float*)d_in[16];
    const float* fc_b     = (const float*)d_in[17];
    const int*   s_ln     = (const int*)d_in[18];
    const int*   q_ln     = (const int*)d_in[19];
    float* out = (float*)d_out;

    __nv_bfloat16 *abf, *bbf;
    cudaGetSymbolAddress((void**)&abf, g_Abf);
    cudaGetSymbolAddress((void**)&bbf, g_Bbf);

    // 0) fp32 -> bf16 hi/lo split: inputs (S then Q rows) and weights (Wih_f | Wih_b)
    convert_split<<<40960, 256>>>(feats_S, abf, abf + AELEMS);
    convert_split<<<8192, 256>>>(feats_Q, abf + (size_t)10240 * DIN,
                                 abf + AELEMS + (size_t)10240 * DIN);
    convert_split<<<3072, 256>>>(Wih_f, bbf, bbf + BELEMS);
    convert_split<<<3072, 256>>>(Wih_b, bbf + (size_t)768 * DIN,
                                 bbf + BELEMS + (size_t)768 * DIN);

    // 1) input projections via bf16-split mma.sync: [12288,4096] x [4096,1536]
    cudaFuncSetAttribute(gemm_mma, cudaFuncAttributeMaxDynamicSharedMemorySize, GMM_SMEM);
    gemm_mma<<<dim3(12, 96), 256, GMM_SMEM>>>(bih_f, bih_b);

    // 2) bidirectional GRU recurrence over all 192 sequences
    bigru_scan<<<48, 256>>>(Whh_f, bhh_f, Whh_b, bhh_b);

    // 3) keys = W_attn(F_S) + bias : [10240,512] x [512,512]
    gemm_keys<<<dim3(80, 4), 256>>>(W_attn, attn_b, 10240, 512, 512);

    // 4) scores -> softmax -> A -> Hc -> (cos,euc)
    cudaFuncSetAttribute(attn_kernel, cudaFuncAttributeMaxDynamicSharedMemorySize, ATTN_SMEM);
    attn_kernel<<<160, 256, ATTN_SMEM>>>(s_ln, q_ln, out);

    // 5) dml GRU over (cos,euc) + sigmoid(FC)
    dml_kernel<<<40, 256>>>(dml_Wih, dml_Whh, dml_bih, dml_bhh, fc_W, fc_b, out);
}

// round 5
// speedup vs baseline: 1.3838x; 1.0119x over previous
#include <cuda_runtime.h>
#include <cuda_bf16.h>
#include <math.h>
#include <stdint.h>

// ---------------- problem constants ----------------
#define KK 5
#define BB 32
#define TT 64
#define DIN 4096
#define HH 256            // GRU hidden
#define H2 512            // 2*H
#define NSEQ 192          // 160 S-sequences + 32 Q-sequences
#define NS 160            // K*B
#define MTOT 12288        // NSEQ*TT rows
#define NTOT 1536         // 3H fwd | 3H bwd
#define ATTN_SMEM ((64*65*3 + 64*520)*4)

#define AELEMS ((size_t)MTOT * DIN)
#define BELEMS ((size_t)NTOT * DIN)

// mma-GEMM tiling: plain bf16 GEMM over K' = 3*4096 (split planes folded into K)
#define BKC 32
#define NCHUNK (3 * DIN / BKC)       // 384
#define TILE_B (128 * 80)            // 10240 bytes: 128 rows x (32+8 pad) bf16
#define STAGE_B (2 * TILE_B)         // A tile + B tile = 20480
#define STAGES 3
#define GMM_SMEM (STAGES * STAGE_B)  // 61440

// ---------------- scratch (device globals; no allocation allowed) ----------------
__device__ float g_XP[(size_t)NSEQ * TT * NTOT];   // input projections, fwd|bwd gates
__device__ float g_F [(size_t)NSEQ * TT * H2];     // BiGRU features [n][t][fwd256|bwd256]
__device__ float g_keys[(size_t)NS * TT * H2];     // W_attn(F_S)+bias
__device__ float g_diff[(size_t)NS * TT * 2];      // (cos, euc) dml inputs
__device__ __nv_bfloat16 g_Abf[2 * AELEMS];        // bf16 hi|lo planes of inputs
__device__ __nv_bfloat16 g_Bbf[2 * BELEMS];        // bf16 hi|lo planes of Wih_f|Wih_b

__device__ __forceinline__ float sigm(float x) { return 1.f / (1.f + expf(-x)); }

__device__ __forceinline__ uint32_t smem_u32(const void* p) {
    uint32_t a;
    asm("{ .reg .u64 t; cvta.to.shared.u64 t, %1; cvt.u32.u64 %0, t; }" : "=r"(a) : "l"(p));
    return a;
}
__device__ __forceinline__ void ldsm4(uint32_t* r, uint32_t a) {
    asm volatile("ldmatrix.sync.aligned.m8n8.x4.shared.b16 {%0,%1,%2,%3}, [%4];"
        : "=r"(r[0]), "=r"(r[1]), "=r"(r[2]), "=r"(r[3]) : "r"(a));
}
__device__ __forceinline__ void mma_bf16(float* c, const uint32_t* a, uint32_t b0, uint32_t b1) {
    asm volatile("mma.sync.aligned.m16n8k16.row.col.f32.bf16.bf16.f32 "
        "{%0,%1,%2,%3}, {%4,%5,%6,%7}, {%8,%9}, {%0,%1,%2,%3};"
        : "+f"(c[0]), "+f"(c[1]), "+f"(c[2]), "+f"(c[3])
        : "r"(a[0]), "r"(a[1]), "r"(a[2]), "r"(a[3]), "r"(b0), "r"(b1));
}
__device__ __forceinline__ void cpasync16(uint32_t s, const void* g) {
    asm volatile("cp.async.cg.shared.global [%0], [%1], 16;" :: "r"(s), "l"(g));
}
#define CP_COMMIT() asm volatile("cp.async.commit_group;" ::: "memory")

// packed f32x2 fma
__device__ __forceinline__ void ffma2(uint64_t& acc, uint64_t a, uint64_t b) {
    asm("fma.rn.f32x2 %0, %1, %2, %0;" : "+l"(acc) : "l"(a), "l"(b));
}
__device__ __forceinline__ float upk_sum(uint64_t v) {
    float x, y;
    asm("mov.b64 {%0,%1}, %2;" : "=f"(x), "=f"(y) : "l"(v));
    return x + y;
}

// ---------------- fp32 -> bf16 hi/lo split ----------------
__global__ void __launch_bounds__(256) convert_split(
    const float* __restrict__ src, __nv_bfloat16* __restrict__ hi, __nv_bfloat16* __restrict__ lo)
{
    size_t i = ((size_t)blockIdx.x * 256 + threadIdx.x) * 4;
    float4 v = *(const float4*)(src + i);
    float vv[4] = { v.x, v.y, v.z, v.w };
    union { __nv_bfloat16 b[4]; uint2 u; } H, L;
#pragma unroll
    for (int j = 0; j < 4; j++) {
        H.b[j] = __float2bfloat16(vv[j]);
        L.b[j] = __float2bfloat16(vv[j] - __bfloat162float(H.b[j]));
    }
    *(uint2*)(hi + i) = H.u;
    *(uint2*)(lo + i) = L.u;
}

// ---------------- bf16 GEMM via mma.sync, K'=12288 (split folded into K) ----------------
// grid (12 N-tiles fastest, 96 M-tiles), 256 threads, tile 128x128, 3-stage cp.async.
__global__ void __launch_bounds__(256, 2) gemm_mma(
    const float* __restrict__ bias1, const float* __restrict__ bias2)
{
    extern __shared__ __align__(128) char smem[];
    uint32_t sbase = smem_u32(smem);
    int tid = threadIdx.x;
    int wid = tid >> 5, lane = tid & 31;
    int warp_m = wid & 1, warp_n = wid >> 1;
    int bn = blockIdx.x * 128, bm = blockIdx.y * 128;

    float acc[4][4][4];
#pragma unroll
    for (int i = 0; i < 4; i++)
#pragma unroll
        for (int j = 0; j < 4; j++)
#pragma unroll
            for (int c = 0; c < 4; c++) acc[i][j][c] = 0.f;

    auto load_stage = [&](int ci, int s) {
        int p = ci % 3;                 // plane phase: 0 Ah*Bh, 1 Ah*Bl, 2 Al*Bh
        int k0 = (ci / 3) * BKC;
        const __nv_bfloat16* Ap = g_Abf + (p == 2 ? AELEMS : 0);
        const __nv_bfloat16* Bp = g_Bbf + (p == 1 ? BELEMS : 0);
        uint32_t sb_s = sbase + s * STAGE_B;
#pragma unroll
        for (int l = 0; l < 4; l++) {
            int idx = tid + l * 256;          // 0..1023
            int isB = idx >> 9;
            int r = (idx >> 2) & 127;
            int seg = idx & 3;
            uint32_t sa = sb_s + isB * TILE_B + r * 80 + seg * 16;
            const __nv_bfloat16* gp = isB
                ? Bp + (size_t)(bn + r) * DIN + k0 + seg * 8
                : Ap + (size_t)(bm + r) * DIN + k0 + seg * 8;
            cpasync16(sa, gp);
        }
        CP_COMMIT();
    };

    auto compute_stage = [&](int s) {
        uint32_t base = sbase + s * STAGE_B;
#pragma unroll
        for (int kh = 0; kh < 2; kh++) {
            uint32_t af[16], bf_[8];
#pragma unroll
            for (int mf = 0; mf < 4; mf++) {
                int row = warp_m * 64 + mf * 16 + (lane & 7) + ((lane >> 3) & 1) * 8;
                uint32_t ad = base + row * 80 + kh * 32 + ((lane >> 4) & 1) * 16;
                ldsm4(&af[mf * 4], ad);
            }
#pragma unroll
            for (int nf2 = 0; nf2 < 2; nf2++) {
                int row = warp_n * 32 + nf2 * 16 + ((lane >> 4) & 1) * 8 + (lane & 7);
                uint32_t bd = base + TILE_B + row * 80 + kh * 32 + ((lane >> 3) & 1) * 16;
                ldsm4(&bf_[nf2 * 4], bd);
            }
#pragma unroll
            for (int mf = 0; mf < 4; mf++)
#pragma unroll
                for (int nf = 0; nf < 4; nf++) {
                    int bi = (nf >> 1) * 4 + (nf & 1) * 2;
                    mma_bf16(acc[mf][nf], &af[mf * 4], bf_[bi], bf_[bi + 1]);
                }
        }
    };

    load_stage(0, 0);
    load_stage(1, 1);

#pragma unroll 1
    for (int ci = 0; ci < NCHUNK; ci++) {
        if (ci < NCHUNK - 1) asm volatile("cp.async.wait_group 1;" ::: "memory");
        else                 asm volatile("cp.async.wait_group 0;" ::: "memory");
        __syncthreads();
        if (ci + 2 < NCHUNK) load_stage(ci + 2, (ci + 2) % STAGES);
        compute_stage(ci % STAGES);
    }

    // epilogue: add bias, write fp32
    float bcol[4][2];
#pragma unroll
    for (int nf = 0; nf < 4; nf++) {
        int col = bn + warp_n * 32 + nf * 8 + (lane & 3) * 2;
        bcol[nf][0] = (col < 768) ? bias1[col] : bias2[col - 768];
        bcol[nf][1] = (col + 1 < 768) ? bias1[col + 1] : bias2[col + 1 - 768];
    }
#pragma unroll
    for (int mf = 0; mf < 4; mf++) {
        int m = bm + warp_m * 64 + mf * 16 + (lane >> 2);
#pragma unroll
        for (int nf = 0; nf < 4; nf++) {
            size_t o = (size_t)m * NTOT + bn + warp_n * 32 + nf * 8 + (lane & 3) * 2;
            float2 v0 = { acc[mf][nf][0] + bcol[nf][0], acc[mf][nf][1] + bcol[nf][1] };
            *(float2*)(g_XP + o) = v0;
            float2 v1 = { acc[mf][nf][2] + bcol[nf][0], acc[mf][nf][3] + bcol[nf][1] };
            *(float2*)(g_XP + o + (size_t)8 * NTOT) = v1;
        }
    }
}

// ---------------- fp32 tiled GEMM for keys: C[m][g] = F[m]·W_attn[g] + bias ----------------
__global__ void __launch_bounds__(256) gemm_keys(
    const float* __restrict__ B1, const float* __restrict__ bias1, int M, int N, int K)
{
    __shared__ float As[16][128];
    __shared__ float Bs[16][128];
    float* C = g_keys;
    int bm = blockIdx.x * 128, bn = blockIdx.y * 128;
    int tid = threadIdx.x;
    int tx = tid & 15, ty = tid >> 4;
    float acc[8][8];
#pragma unroll
    for (int i = 0; i < 8; i++)
#pragma unroll
        for (int j = 0; j < 8; j++) acc[i][j] = 0.f;

    for (int k0 = 0; k0 < K; k0 += 16) {
#pragma unroll
        for (int l = 0; l < 2; l++) {
            int idx = tid + l * 256;
            int row = idx >> 2;
            int col = (idx & 3) * 4;
            float4 v = *(const float4*)(g_F + (size_t)(bm + row) * K + k0 + col);
            As[col + 0][row] = v.x; As[col + 1][row] = v.y;
            As[col + 2][row] = v.z; As[col + 3][row] = v.w;
            float4 w = *(const float4*)(B1 + (size_t)(bn + row) * K + k0 + col);
            Bs[col + 0][row] = w.x; Bs[col + 1][row] = w.y;
            Bs[col + 2][row] = w.z; Bs[col + 3][row] = w.w;
        }
        __syncthreads();
#pragma unroll
        for (int kk = 0; kk < 16; kk++) {
            float a[8], b[8];
#pragma unroll
            for (int i = 0; i < 8; i++) a[i] = As[kk][ty * 8 + i];
#pragma unroll
            for (int j = 0; j < 8; j++) b[j] = Bs[kk][tx * 8 + j];
#pragma unroll
            for (int i = 0; i < 8; i++)
#pragma unroll
                for (int j = 0; j < 8; j++) acc[i][j] += a[i] * b[j];
        }
        __syncthreads();
    }
#pragma unroll
    for (int i = 0; i < 8; i++) {
        int m = bm + ty * 8 + i;
#pragma unroll
        for (int j = 0; j < 8; j++) {
            int g = bn + tx * 8 + j;
            C[(size_t)m * N + g] = acc[i][j] + bias1[g];
        }
    }
}

// ---------------- BiGRU recurrent scan: 48 blocks x 4 sequences, 256 threads ----------------
__global__ void __launch_bounds__(256) bigru_scan(
    const float* __restrict__ Whh_f, const float* __restrict__ bhh_f,
    const float* __restrict__ Whh_b, const float* __restrict__ bhh_b)
{
    __shared__ __align__(16) float sh[2][4][256];
    int tid = threadIdx.x;
    int nb = blockIdx.x * 4;

#pragma unroll
    for (int d = 0; d < 2; d++)
#pragma unroll
        for (int s = 0; s < 4; s++) sh[d][s][tid] = 0.f;
    __syncthreads();

    const float* W[2]  = { Whh_f, Whh_b };
    const float* BH[2] = { bhh_f, bhh_b };
    float bh_r[2], bh_z[2], bh_n[2];
#pragma unroll
    for (int d = 0; d < 2; d++) {
        bh_r[d] = BH[d][tid]; bh_z[d] = BH[d][256 + tid]; bh_n[d] = BH[d][512 + tid];
    }

    for (int t = 0; t < 64; t++) {
        float hn[2][4];
#pragma unroll
        for (int d = 0; d < 2; d++) {
            int tt = d ? (63 - t) : t;
            const float* wr = W[d] + (size_t)tid * 256;
            const float* wz = W[d] + (size_t)(256 + tid) * 256;
            const float* wn = W[d] + (size_t)(512 + tid) * 256;
            uint64_t ar[4] = {0,0,0,0}, az[4] = {0,0,0,0}, an[4] = {0,0,0,0};
            for (int i = 0; i < 256; i += 4) {
                ulonglong2 r2 = *(const ulonglong2*)(wr + i);
                ulonglong2 z2 = *(const ulonglong2*)(wz + i);
                ulonglong2 n2 = *(const ulonglong2*)(wn + i);
#pragma unroll
                for (int s = 0; s < 4; s++) {
                    ulonglong2 h2 = *(const ulonglong2*)(&sh[d][s][i]);
                    ffma2(ar[s], r2.x, h2.x); ffma2(ar[s], r2.y, h2.y);
                    ffma2(az[s], z2.x, h2.x); ffma2(az[s], z2.y, h2.y);
                    ffma2(an[s], n2.x, h2.x); ffma2(an[s], n2.y, h2.y);
                }
            }
#pragma unroll
            for (int s = 0; s < 4; s++) {
                int n = nb + s;
                const float* xp = g_XP + ((size_t)n * 64 + tt) * NTOT + d * 768;
                float r  = sigm(xp[tid]       + upk_sum(ar[s]) + bh_r[d]);
                float z  = sigm(xp[256 + tid] + upk_sum(az[s]) + bh_z[d]);
                float ng = tanhf(xp[512 + tid] + r * (upk_sum(an[s]) + bh_n[d]));
                hn[d][s] = (1.f - z) * ng + z * sh[d][s][tid];
            }
        }
        __syncthreads();
#pragma unroll
        for (int d = 0; d < 2; d++) {
            int tt = d ? (63 - t) : t;
#pragma unroll
            for (int s = 0; s < 4; s++) {
                sh[d][s][tid] = hn[d][s];
                g_F[((size_t)(nb + s) * 64 + tt) * 512 + d * 256 + tid] = hn[d][s];
            }
        }
        __syncthreads();
    }
}

// ---------------- attention + softmax + Hc + cos/euc, one block per (k,b) ----------------
__global__ void __launch_bounds__(256) attn_kernel(
    const int* __restrict__ s_ln_arr, const int* __restrict__ q_ln_arr,
    float* __restrict__ d_out)
{
    extern __shared__ float sm[];
    float* ssc = sm;                 // [64][65] scores -> A
    float* sk  = sm + 64 * 65;       // [64][65] keys tile
    float* sq  = sk + 64 * 65;       // [64][65] F_Q tile
    float* shc = sq + 64 * 65;       // [64][520] Hc

    int kb = blockIdx.x;
    int b = kb & 31;
    int tid = threadIdx.x;
    int q_ln = q_ln_arr[b];
    int s_ln = s_ln_arr[kb];

    const float* keys = g_keys + (size_t)kb * 64 * 512;
    const float* FQ   = g_F + ((size_t)(160 + b) * 64) * 512;
    const float* FS   = g_F + ((size_t)kb * 64) * 512;

    int tx = tid & 15, ty = tid >> 4;
    float acc[4][4];
#pragma unroll
    for (int i = 0; i < 4; i++)
#pragma unroll
        for (int j = 0; j < 4; j++) acc[i][j] = 0.f;

    for (int g0 = 0; g0 < 512; g0 += 64) {
#pragma unroll
        for (int l = 0; l < 4; l++) {
            int idx = tid + l * 256;
            int row = idx >> 4;
            int col = (idx & 15) * 4;
            float4 v = *(const float4*)(keys + row * 512 + g0 + col);
            float* dk = sk + row * 65 + col;
            dk[0] = v.x; dk[1] = v.y; dk[2] = v.z; dk[3] = v.w;
            float4 w = *(const float4*)(FQ + row * 512 + g0 + col);
            float* dq = sq + row * 65 + col;
            dq[0] = w.x; dq[1] = w.y; dq[2] = w.z; dq[3] = w.w;
        }
        __syncthreads();
        for (int g = 0; g < 64; g++) {
            float a[4], bq[4];
#pragma unroll
            for (int i = 0; i < 4; i++) a[i]  = sk[(ty * 4 + i) * 65 + g];
#pragma unroll
            for (int j = 0; j < 4; j++) bq[j] = sq[(tx * 4 + j) * 65 + g];
#pragma unroll
            for (int i = 0; i < 4; i++)
#pragma unroll
                for (int j = 0; j < 4; j++) acc[i][j] += a[i] * bq[j];
        }
        __syncthreads();
    }
#pragma unroll
    for (int i = 0; i < 4; i++)
#pragma unroll
        for (int j = 0; j < 4; j++) {
            int s = ty * 4 + i, q = tx * 4 + j;
            ssc[s * 65 + q] = (q < q_ln) ? acc[i][j] : -INFINITY;
        }
    __syncthreads();

    int warp = tid >> 5, lane = tid & 31;
    for (int si = 0; si < 8; si++) {
        int s = warp * 8 + si;
        float v0 = ssc[s * 65 + lane];
        float v1 = ssc[s * 65 + 32 + lane];
        float mx = fmaxf(v0, v1);
#pragma unroll
        for (int o = 16; o > 0; o >>= 1) mx = fmaxf(mx, __shfl_xor_sync(~0u, mx, o));
        float e0 = expf(v0 - mx), e1 = expf(v1 - mx);
        float su = e0 + e1;
#pragma unroll
        for (int o = 16; o > 0; o >>= 1) su += __shfl_xor_sync(~0u, su, o);
        float sc = (s < s_ln) ? (1.f / su) : 0.f;
        ssc[s * 65 + lane] = e0 * sc;
        ssc[s * 65 + 32 + lane] = e1 * sc;
    }
    __syncthreads();

    if (kb == NS - 1) {
        for (int i = tid; i < 4096; i += 256)
            d_out[i] = ssc[(i >> 6) * 65 + (i & 63)];
    }

    int hcol = tid & 63;
    int qgrp = tid >> 6;
#pragma unroll
    for (int pass = 0; pass < 2; pass++) {
        int qb = qgrp * 8 + pass * 32;
        float hc[8][8];
#pragma unroll
        for (int qi = 0; qi < 8; qi++)
#pragma unroll
            for (int hj = 0; hj < 8; hj++) hc[qi][hj] = 0.f;
        for (int s = 0; s < 64; s++) {
            float4 f0 = *(const float4*)(FS + s * 512 + hcol * 8);
            float4 f1 = *(const float4*)(FS + s * 512 + hcol * 8 + 4);
#pragma unroll
            for (int qi = 0; qi < 8; qi++) {
                float a = ssc[s * 65 + qb + qi];
                hc[qi][0] += a * f0.x; hc[qi][1] += a * f0.y;
                hc[qi][2] += a * f0.z; hc[qi][3] += a * f0.w;
                hc[qi][4] += a * f1.x; hc[qi][5] += a * f1.y;
                hc[qi][6] += a * f1.z; hc[qi][7] += a * f1.w;
            }
        }
#pragma unroll
        for (int qi = 0; qi < 8; qi++) {
            float* dst = shc + (qb + qi) * 520 + hcol * 8;
#pragma unroll
            for (int hj = 0; hj < 8; hj++) dst[hj] = hc[qi][hj];
        }
    }
    __syncthreads();

    for (int qi = 0; qi < 8; qi++) {
        int q = warp + qi * 8;
        float dot = 0.f, nq = 0.f, nh = 0.f, ee = 0.f;
        for (int c = 0; c < 16; c++) {
            int h = lane + c * 32;
            float fq = FQ[q * 512 + h];
            float hv = shc[q * 520 + h];
            dot += fq * hv; nq += fq * fq; nh += hv * hv;
            float dd = fq - hv; ee += dd * dd;
        }
#pragma unroll
        for (int o = 16; o > 0; o >>= 1) {
            dot += __shfl_xor_sync(~0u, dot, o);
            nq  += __shfl_xor_sync(~0u, nq,  o);
            nh  += __shfl_xor_sync(~0u, nh,  o);
            ee  += __shfl_xor_sync(~0u, ee,  o);
        }
        if (lane == 0) {
            float cosv = dot / fmaxf(sqrtf(nq) * sqrtf(nh), 1e-6f);
            float eucv = sqrtf(ee);
            float msk = (q < q_ln) ? 1.f : 0.f;
            g_diff[((size_t)kb * 64 + q) * 2 + 0] = cosv * msk;
            g_diff[((size_t)kb * 64 + q) * 2 + 1] = eucv * msk;
        }
    }
}

// ---------------- dml GRU over diff + FC head: 40 blocks x 4 sequences ----------------
__global__ void __launch_bounds__(256) dml_kernel(
    const float* __restrict__ Wih, const float* __restrict__ Whh,
    const float* __restrict__ bih, const float* __restrict__ bhh,
    const float* __restrict__ fcW, const float* __restrict__ fcb,
    float* __restrict__ d_out)
{
    __shared__ __align__(16) float sh[4][256];
    __shared__ float red[256];
    int tid = threadIdx.x;
    int nb = blockIdx.x * 4;

#pragma unroll
    for (int s = 0; s < 4; s++) sh[s][tid] = 0.f;
    __syncthreads();

    float wi_r0 = Wih[tid * 2],         wi_r1 = Wih[tid * 2 + 1];
    float wi_z0 = Wih[(256 + tid) * 2], wi_z1 = Wih[(256 + tid) * 2 + 1];
    float wi_n0 = Wih[(512 + tid) * 2], wi_n1 = Wih[(512 + tid) * 2 + 1];
    float bi_r = bih[tid], bi_z = bih[256 + tid], bi_n = bih[512 + tid];
    float bh_r = bhh[tid], bh_z = bhh[256 + tid], bh_n = bhh[512 + tid];
    const float* wr = Whh + (size_t)tid * 256;
    const float* wz = Whh + (size_t)(256 + tid) * 256;
    const float* wn = Whh + (size_t)(512 + tid) * 256;

    for (int t = 0; t < 64; t++) {
        uint64_t ar[4] = {0,0,0,0}, az[4] = {0,0,0,0}, an[4] = {0,0,0,0};
        for (int i = 0; i < 256; i += 4) {
            ulonglong2 r2 = *(const ulonglong2*)(wr + i);
            ulonglong2 z2 = *(const ulonglong2*)(wz + i);
            ulonglong2 n2 = *(const ulonglong2*)(wn + i);
#pragma unroll
            for (int s = 0; s < 4; s++) {
                ulonglong2 h2 = *(const ulonglong2*)(&sh[s][i]);
                ffma2(ar[s], r2.x, h2.x); ffma2(ar[s], r2.y, h2.y);
                ffma2(az[s], z2.x, h2.x); ffma2(az[s], z2.y, h2.y);
                ffma2(an[s], n2.x, h2.x); ffma2(an[s], n2.y, h2.y);
            }
        }
        float hn[4];
#pragma unroll
        for (int s = 0; s < 4; s++) {
            int n = nb + s;
            float d0 = g_diff[((size_t)n * 64 + t) * 2 + 0];
            float d1 = g_diff[((size_t)n * 64 + t) * 2 + 1];
            float xr = wi_r0 * d0 + wi_r1 * d1 + bi_r;
            float xz = wi_z0 * d0 + wi_z1 * d1 + bi_z;
            float xn = wi_n0 * d0 + wi_n1 * d1 + bi_n;
            float r  = sigm(xr + upk_sum(ar[s]) + bh_r);
            float z  = sigm(xz + upk_sum(az[s]) + bh_z);
            float ng = tanhf(xn + r * (upk_sum(an[s]) + bh_n));
            hn[s] = (1.f - z) * ng + z * sh[s][tid];
        }
        __syncthreads();
#pragma unroll
        for (int s = 0; s < 4; s++) sh[s][tid] = hn[s];
        __syncthreads();
    }

    float fw = fcW[tid];
    for (int s = 0; s < 4; s++) {
        int n = nb + s;
        red[tid] = fw * sh[s][tid];
        __syncthreads();
        for (int off = 128; off > 0; off >>= 1) {
            if (tid < off) red[tid] += red[tid + off];
            __syncthreads();
        }
        if (tid == 0)
            d_out[4096 + n] = sigm(red[0] + fcb[0]);
        __syncthreads();
    }
}

// ---------------- launcher ----------------
extern "C" void kernel_launch(void* const* d_in, const int* in_sizes, int n_in,
                              void* d_out, int out_size)
{
    const float* feats_S  = (const float*)d_in[0];
    const float* feats_Q  = (const float*)d_in[1];
    const float* Wih_f    = (const float*)d_in[2];
    const float* Whh_f    = (const float*)d_in[3];
    const float* bih_f    = (const float*)d_in[4];
    const float* bhh_f    = (const float*)d_in[5];
    const float* Wih_b    = (const float*)d_in[6];
    const float* Whh_b    = (const float*)d_in[7];
    const float* bih_b    = (const float*)d_in[8];
    const float* bhh_b    = (const float*)d_in[9];
    const float* W_attn   = (const float*)d_in[10];
    const float* attn_b   = (const float*)d_in[11];
    const float* dml_Wih  = (const float*)d_in[12];
    const float* dml_Whh  = (const float*)d_in[13];
    const float* dml_bih  = (const float*)d_in[14];
    const float* dml_bhh  = (const float*)d_in[15];
    const float* fc_W     = (const float*)d_in[16];
    const float* fc_b     = (const float*)d_in[17];
    const int*   s_ln     = (const int*)d_in[18];
    const int*   q_ln     = (const int*)d_in[19];
    float* out = (float*)d_out;

    __nv_bfloat16 *abf, *bbf;
    cudaGetSymbolAddress((void**)&abf, g_Abf);
    cudaGetSymbolAddress((void**)&bbf, g_Bbf);

    // 0) fp32 -> bf16 hi/lo split: inputs (S then Q rows) and weights (Wih_f | Wih_b)
    convert_split<<<40960, 256>>>(feats_S, abf, abf + AELEMS);
    convert_split<<<8192, 256>>>(feats_Q, abf + (size_t)10240 * DIN,
                                 abf + AELEMS + (size_t)10240 * DIN);
    convert_split<<<3072, 256>>>(Wih_f, bbf, bbf + BELEMS);
    convert_split<<<3072, 256>>>(Wih_b, bbf + (size_t)768 * DIN,
                                 bbf + BELEMS + (size_t)768 * DIN);

    // 1) input projections via bf16 mma.sync, split folded into K': [12288,12288] x -> [12288,1536]
    cudaFuncSetAttribute(gemm_mma, cudaFuncAttributeMaxDynamicSharedMemorySize, GMM_SMEM);
    gemm_mma<<<dim3(12, 96), 256, GMM_SMEM>>>(bih_f, bih_b);

    // 2) bidirectional GRU recurrence over all 192 sequences
    bigru_scan<<<48, 256>>>(Whh_f, bhh_f, Whh_b, bhh_b);

    // 3) keys = W_attn(F_S) + bias : [10240,512] x [512,512]
    gemm_keys<<<dim3(80, 4), 256>>>(W_attn, attn_b, 10240, 512, 512);

    // 4) scores -> softmax -> A -> Hc -> (cos,euc)
    cudaFuncSetAttribute(attn_kernel, cudaFuncAttributeMaxDynamicSharedMemorySize, ATTN_SMEM);
    attn_kernel<<<160, 256, ATTN_SMEM>>>(s_ln, q_ln, out);

    // 5) dml GRU over (cos,euc) + sigmoid(FC)
    dml_kernel<<<40, 256>>>(dml_Wih, dml_Whh, dml_bih, dml_bhh, fc_W, fc_b, out);
}

// round 6
// speedup vs baseline: 1.9389x; 1.4012x over previous
#include <cuda_runtime.h>
#include <cuda_bf16.h>
#include <math.h>
#include <stdint.h>

// ---------------- problem constants ----------------
#define KK 5
#define BB 32
#define TT 64
#define DIN 4096
#define HH 256            // GRU hidden
#define H2 512            // 2*H
#define NSEQ 192          // 160 S-sequences + 32 Q-sequences
#define NS 160            // K*B
#define MTOT 12288        // NSEQ*TT rows
#define NTOT 1536         // 3H fwd | 3H bwd
#define ATTN_SMEM ((64*65*3 + 64*520)*4)

#define AELEMS ((size_t)MTOT * DIN)
#define BELEMS ((size_t)NTOT * DIN)

// mma-GEMM tiling: plain bf16 GEMM over K' = 3*4096 (split planes folded into K)
#define BKC 64
#define NCHUNK (3 * DIN / BKC)       // 192
#define TILE_B (128 * 144)           // 18432 B: 128 rows x (64+8 pad) bf16
#define STAGE_B (2 * TILE_B)         // A tile + B tile = 36864
#define STAGES 3
#define GMM_SMEM (STAGES * STAGE_B)  // 110592 (2 CTAs/SM)

// ---------------- scratch (device globals; no allocation allowed) ----------------
__device__ float g_XP[(size_t)NSEQ * TT * NTOT];   // input projections, fwd|bwd gates
__device__ float g_F [(size_t)NSEQ * TT * H2];     // BiGRU features [n][t][fwd256|bwd256]
__device__ float g_keys[(size_t)NS * TT * H2];     // W_attn(F_S)+bias
__device__ float g_diff[(size_t)NS * TT * 2];      // (cos, euc) dml inputs
__device__ __nv_bfloat16 g_Abf[2 * AELEMS];        // bf16 hi|lo planes of inputs
__device__ __nv_bfloat16 g_Bbf[2 * BELEMS];        // bf16 hi|lo planes of Wih_f|Wih_b

__device__ __forceinline__ float sigm(float x) { return 1.f / (1.f + expf(-x)); }

__device__ __forceinline__ uint32_t smem_u32(const void* p) {
    uint32_t a;
    asm("{ .reg .u64 t; cvta.to.shared.u64 t, %1; cvt.u32.u64 %0, t; }" : "=r"(a) : "l"(p));
    return a;
}
__device__ __forceinline__ void ldsm4(uint32_t* r, uint32_t a) {
    asm volatile("ldmatrix.sync.aligned.m8n8.x4.shared.b16 {%0,%1,%2,%3}, [%4];"
        : "=r"(r[0]), "=r"(r[1]), "=r"(r[2]), "=r"(r[3]) : "r"(a));
}
__device__ __forceinline__ void mma_bf16(float* c, const uint32_t* a, uint32_t b0, uint32_t b1) {
    asm volatile("mma.sync.aligned.m16n8k16.row.col.f32.bf16.bf16.f32 "
        "{%0,%1,%2,%3}, {%4,%5,%6,%7}, {%8,%9}, {%0,%1,%2,%3};"
        : "+f"(c[0]), "+f"(c[1]), "+f"(c[2]), "+f"(c[3])
        : "r"(a[0]), "r"(a[1]), "r"(a[2]), "r"(a[3]), "r"(b0), "r"(b1));
}
__device__ __forceinline__ void cpasync16(uint32_t s, const void* g) {
    asm volatile("cp.async.cg.shared.global [%0], [%1], 16;" :: "r"(s), "l"(g));
}
#define CP_COMMIT() asm volatile("cp.async.commit_group;" ::: "memory")

// packed f32x2 fma
__device__ __forceinline__ void ffma2(uint64_t& acc, uint64_t a, uint64_t b) {
    asm("fma.rn.f32x2 %0, %1, %2, %0;" : "+l"(acc) : "l"(a), "l"(b));
}
__device__ __forceinline__ float upk_sum(uint64_t v) {
    float x, y;
    asm("mov.b64 {%0,%1}, %2;" : "=f"(x), "=f"(y) : "l"(v));
    return x + y;
}

// ---------------- fp32 -> bf16 hi/lo split ----------------
__global__ void __launch_bounds__(256) convert_split(
    const float* __restrict__ src, __nv_bfloat16* __restrict__ hi, __nv_bfloat16* __restrict__ lo)
{
    size_t i = ((size_t)blockIdx.x * 256 + threadIdx.x) * 4;
    float4 v = *(const float4*)(src + i);
    float vv[4] = { v.x, v.y, v.z, v.w };
    union { __nv_bfloat16 b[4]; uint2 u; } H, L;
#pragma unroll
    for (int j = 0; j < 4; j++) {
        H.b[j] = __float2bfloat16(vv[j]);
        L.b[j] = __float2bfloat16(vv[j] - __bfloat162float(H.b[j]));
    }
    *(uint2*)(hi + i) = H.u;
    *(uint2*)(lo + i) = L.u;
}

// both weight matrices in ONE launch (keeps gemm_mma at launch slot #4 for ncu)
__global__ void __launch_bounds__(256) convert_w(
    const float* __restrict__ wf, const float* __restrict__ wb,
    __nv_bfloat16* __restrict__ hi, __nv_bfloat16* __restrict__ lo)
{
    int bb = blockIdx.x;
    const float* src = wf;
    size_t off = 0;
    if (bb >= 3072) { src = wb; off = (size_t)768 * DIN; bb -= 3072; }
    size_t i = ((size_t)bb * 256 + threadIdx.x) * 4;
    float4 v = *(const float4*)(src + i);
    float vv[4] = { v.x, v.y, v.z, v.w };
    union { __nv_bfloat16 b[4]; uint2 u; } H, L;
#pragma unroll
    for (int j = 0; j < 4; j++) {
        H.b[j] = __float2bfloat16(vv[j]);
        L.b[j] = __float2bfloat16(vv[j] - __bfloat162float(H.b[j]));
    }
    *(uint2*)(hi + off + i) = H.u;
    *(uint2*)(lo + off + i) = L.u;
}

// ---------------- bf16 GEMM via mma.sync, K'=12288, BK=64, 3-stage cp.async ----------------
// grid (12 N-tiles fastest, 96 M-tiles), 256 threads, tile 128x128.
__global__ void __launch_bounds__(256, 2) gemm_mma(
    const float* __restrict__ bias1, const float* __restrict__ bias2)
{
    extern __shared__ __align__(128) char smem[];
    uint32_t sbase = smem_u32(smem);
    int tid = threadIdx.x;
    int wid = tid >> 5, lane = tid & 31;
    int warp_m = wid & 1, warp_n = wid >> 1;
    int bn = blockIdx.x * 128, bm = blockIdx.y * 128;

    float acc[4][4][4];
#pragma unroll
    for (int i = 0; i < 4; i++)
#pragma unroll
        for (int j = 0; j < 4; j++)
#pragma unroll
            for (int c = 0; c < 4; c++) acc[i][j][c] = 0.f;

    auto load_stage = [&](int ci, int s) {
        int p = ci % 3;                 // plane phase: 0 Ah*Bh, 1 Ah*Bl, 2 Al*Bh
        int k0 = (ci / 3) * BKC;
        const __nv_bfloat16* Ap = g_Abf + (p == 2 ? AELEMS : 0);
        const __nv_bfloat16* Bp = g_Bbf + (p == 1 ? BELEMS : 0);
        uint32_t sb_s = sbase + s * STAGE_B;
#pragma unroll
        for (int l = 0; l < 8; l++) {
            int idx = tid + l * 256;          // 0..2047
            int isB = idx >> 10;
            int r = (idx >> 3) & 127;
            int seg = idx & 7;
            uint32_t sa = sb_s + isB * TILE_B + r * 144 + seg * 16;
            const __nv_bfloat16* gp = isB
                ? Bp + (size_t)(bn + r) * DIN + k0 + seg * 8
                : Ap + (size_t)(bm + r) * DIN + k0 + seg * 8;
            cpasync16(sa, gp);
        }
        CP_COMMIT();
    };

    auto compute_stage = [&](int s) {
        uint32_t base = sbase + s * STAGE_B;
#pragma unroll
        for (int kh = 0; kh < 4; kh++) {
            uint32_t af[16], bfr[8];
#pragma unroll
            for (int mf = 0; mf < 4; mf++) {
                int row = warp_m * 64 + mf * 16 + (lane & 7) + ((lane >> 3) & 1) * 8;
                uint32_t ad = base + row * 144 + kh * 32 + ((lane >> 4) & 1) * 16;
                ldsm4(&af[mf * 4], ad);
            }
#pragma unroll
            for (int nf2 = 0; nf2 < 2; nf2++) {
                int row = warp_n * 32 + nf2 * 16 + ((lane >> 4) & 1) * 8 + (lane & 7);
                uint32_t bd = base + TILE_B + row * 144 + kh * 32 + ((lane >> 3) & 1) * 16;
                ldsm4(&bfr[nf2 * 4], bd);
            }
#pragma unroll
            for (int mf = 0; mf < 4; mf++)
#pragma unroll
                for (int nf = 0; nf < 4; nf++) {
                    int bi = (nf >> 1) * 4 + (nf & 1) * 2;
                    mma_bf16(acc[mf][nf], &af[mf * 4], bfr[bi], bfr[bi + 1]);
                }
        }
    };

    load_stage(0, 0);
    load_stage(1, 1);

#pragma unroll 1
    for (int ci = 0; ci < NCHUNK; ci++) {
        if (ci < NCHUNK - 1) asm volatile("cp.async.wait_group 1;" ::: "memory");
        else                 asm volatile("cp.async.wait_group 0;" ::: "memory");
        __syncthreads();
        if (ci + 2 < NCHUNK) load_stage(ci + 2, (ci + 2) % STAGES);
        compute_stage(ci % STAGES);
    }

    // epilogue: add bias, write fp32
    float bcol[4][2];
#pragma unroll
    for (int nf = 0; nf < 4; nf++) {
        int col = bn + warp_n * 32 + nf * 8 + (lane & 3) * 2;
        bcol[nf][0] = (col < 768) ? bias1[col] : bias2[col - 768];
        bcol[nf][1] = (col + 1 < 768) ? bias1[col + 1] : bias2[col + 1 - 768];
    }
#pragma unroll
    for (int mf = 0; mf < 4; mf++) {
        int m = bm + warp_m * 64 + mf * 16 + (lane >> 2);
#pragma unroll
        for (int nf = 0; nf < 4; nf++) {
            size_t o = (size_t)m * NTOT + bn + warp_n * 32 + nf * 8 + (lane & 3) * 2;
            float2 v0 = { acc[mf][nf][0] + bcol[nf][0], acc[mf][nf][1] + bcol[nf][1] };
            *(float2*)(g_XP + o) = v0;
            float2 v1 = { acc[mf][nf][2] + bcol[nf][0], acc[mf][nf][3] + bcol[nf][1] };
            *(float2*)(g_XP + o + (size_t)8 * NTOT) = v1;
        }
    }
}

// ---------------- fp32 tiled GEMM for keys: C[m][g] = F[m]·W_attn[g] + bias ----------------
__global__ void __launch_bounds__(256) gemm_keys(
    const float* __restrict__ B1, const float* __restrict__ bias1, int M, int N, int K)
{
    __shared__ float As[16][128];
    __shared__ float Bs[16][128];
    float* C = g_keys;
    int bm = blockIdx.x * 128, bn = blockIdx.y * 128;
    int tid = threadIdx.x;
    int tx = tid & 15, ty = tid >> 4;
    float acc[8][8];
#pragma unroll
    for (int i = 0; i < 8; i++)
#pragma unroll
        for (int j = 0; j < 8; j++) acc[i][j] = 0.f;

    for (int k0 = 0; k0 < K; k0 += 16) {
#pragma unroll
        for (int l = 0; l < 2; l++) {
            int idx = tid + l * 256;
            int row = idx >> 2;
            int col = (idx & 3) * 4;
            float4 v = *(const float4*)(g_F + (size_t)(bm + row) * K + k0 + col);
            As[col + 0][row] = v.x; As[col + 1][row] = v.y;
            As[col + 2][row] = v.z; As[col + 3][row] = v.w;
            float4 w = *(const float4*)(B1 + (size_t)(bn + row) * K + k0 + col);
            Bs[col + 0][row] = w.x; Bs[col + 1][row] = w.y;
            Bs[col + 2][row] = w.z; Bs[col + 3][row] = w.w;
        }
        __syncthreads();
#pragma unroll
        for (int kk = 0; kk < 16; kk++) {
            float a[8], b[8];
#pragma unroll
            for (int i = 0; i < 8; i++) a[i] = As[kk][ty * 8 + i];
#pragma unroll
            for (int j = 0; j < 8; j++) b[j] = Bs[kk][tx * 8 + j];
#pragma unroll
            for (int i = 0; i < 8; i++)
#pragma unroll
                for (int j = 0; j < 8; j++) acc[i][j] += a[i] * b[j];
        }
        __syncthreads();
    }
#pragma unroll
    for (int i = 0; i < 8; i++) {
        int m = bm + ty * 8 + i;
#pragma unroll
        for (int j = 0; j < 8; j++) {
            int g = bn + tx * 8 + j;
            C[(size_t)m * N + g] = acc[i][j] + bias1[g];
        }
    }
}

// ---------------- GRU recurrent scan: 96 blocks = 24 seq-groups x 2 directions ----------------
__global__ void __launch_bounds__(256) bigru_scan(
    const float* __restrict__ Whh_f, const float* __restrict__ bhh_f,
    const float* __restrict__ Whh_b, const float* __restrict__ bhh_b)
{
    __shared__ __align__(16) float sh[4][256];
    int tid = threadIdx.x;
    int d = blockIdx.x & 1;
    int nb = (blockIdx.x >> 1) * 4;

#pragma unroll
    for (int s = 0; s < 4; s++) sh[s][tid] = 0.f;
    __syncthreads();

    const float* W  = d ? Whh_b : Whh_f;
    const float* BH = d ? bhh_b : bhh_f;
    float bh_r = BH[tid], bh_z = BH[256 + tid], bh_n = BH[512 + tid];
    const float* wr = W + (size_t)tid * 256;
    const float* wz = W + (size_t)(256 + tid) * 256;
    const float* wn = W + (size_t)(512 + tid) * 256;

    for (int t = 0; t < 64; t++) {
        int tt = d ? (63 - t) : t;
        uint64_t ar[4] = {0,0,0,0}, az[4] = {0,0,0,0}, an[4] = {0,0,0,0};
        for (int i = 0; i < 256; i += 4) {
            ulonglong2 r2 = *(const ulonglong2*)(wr + i);
            ulonglong2 z2 = *(const ulonglong2*)(wz + i);
            ulonglong2 n2 = *(const ulonglong2*)(wn + i);
#pragma unroll
            for (int s = 0; s < 4; s++) {
                ulonglong2 h2 = *(const ulonglong2*)(&sh[s][i]);
                ffma2(ar[s], r2.x, h2.x); ffma2(ar[s], r2.y, h2.y);
                ffma2(az[s], z2.x, h2.x); ffma2(az[s], z2.y, h2.y);
                ffma2(an[s], n2.x, h2.x); ffma2(an[s], n2.y, h2.y);
            }
        }
        float hn[4];
#pragma unroll
        for (int s = 0; s < 4; s++) {
            int n = nb + s;
            const float* xp = g_XP + ((size_t)n * 64 + tt) * NTOT + d * 768;
            float r  = sigm(xp[tid]       + upk_sum(ar[s]) + bh_r);
            float z  = sigm(xp[256 + tid] + upk_sum(az[s]) + bh_z);
            float ng = tanhf(xp[512 + tid] + r * (upk_sum(an[s]) + bh_n));
            hn[s] = (1.f - z) * ng + z * sh[s][tid];
        }
        __syncthreads();
#pragma unroll
        for (int s = 0; s < 4; s++) {
            sh[s][tid] = hn[s];
            g_F[((size_t)(nb + s) * 64 + tt) * 512 + d * 256 + tid] = hn[s];
        }
        __syncthreads();
    }
}

// ---------------- attention + softmax + Hc + cos/euc, one block per (k,b) ----------------
__global__ void __launch_bounds__(256) attn_kernel(
    const int* __restrict__ s_ln_arr, const int* __restrict__ q_ln_arr,
    float* __restrict__ d_out)
{
    extern __shared__ float sm[];
    float* ssc = sm;                 // [64][65] scores -> A
    float* sk  = sm + 64 * 65;       // [64][65] keys tile
    float* sq  = sk + 64 * 65;       // [64][65] F_Q tile
    float* shc = sq + 64 * 65;       // [64][520] Hc

    int kb = blockIdx.x;
    int b = kb & 31;
    int tid = threadIdx.x;
    int q_ln = q_ln_arr[b];
    int s_ln = s_ln_arr[kb];

    const float* keys = g_keys + (size_t)kb * 64 * 512;
    const float* FQ   = g_F + ((size_t)(160 + b) * 64) * 512;
    const float* FS   = g_F + ((size_t)kb * 64) * 512;

    int tx = tid & 15, ty = tid >> 4;
    float acc[4][4];
#pragma unroll
    for (int i = 0; i < 4; i++)
#pragma unroll
        for (int j = 0; j < 4; j++) acc[i][j] = 0.f;

    for (int g0 = 0; g0 < 512; g0 += 64) {
#pragma unroll
        for (int l = 0; l < 4; l++) {
            int idx = tid + l * 256;
            int row = idx >> 4;
            int col = (idx & 15) * 4;
            float4 v = *(const float4*)(keys + row * 512 + g0 + col);
            float* dk = sk + row * 65 + col;
            dk[0] = v.x; dk[1] = v.y; dk[2] = v.z; dk[3] = v.w;
            float4 w = *(const float4*)(FQ + row * 512 + g0 + col);
            float* dq = sq + row * 65 + col;
            dq[0] = w.x; dq[1] = w.y; dq[2] = w.z; dq[3] = w.w;
        }
        __syncthreads();
        for (int g = 0; g < 64; g++) {
            float a[4], bq[4];
#pragma unroll
            for (int i = 0; i < 4; i++) a[i]  = sk[(ty * 4 + i) * 65 + g];
#pragma unroll
            for (int j = 0; j < 4; j++) bq[j] = sq[(tx * 4 + j) * 65 + g];
#pragma unroll
            for (int i = 0; i < 4; i++)
#pragma unroll
                for (int j = 0; j < 4; j++) acc[i][j] += a[i] * bq[j];
        }
        __syncthreads();
    }
#pragma unroll
    for (int i = 0; i < 4; i++)
#pragma unroll
        for (int j = 0; j < 4; j++) {
            int s = ty * 4 + i, q = tx * 4 + j;
            ssc[s * 65 + q] = (q < q_ln) ? acc[i][j] : -INFINITY;
        }
    __syncthreads();

    int warp = tid >> 5, lane = tid & 31;
    for (int si = 0; si < 8; si++) {
        int s = warp * 8 + si;
        float v0 = ssc[s * 65 + lane];
        float v1 = ssc[s * 65 + 32 + lane];
        float mx = fmaxf(v0, v1);
#pragma unroll
        for (int o = 16; o > 0; o >>= 1) mx = fmaxf(mx, __shfl_xor_sync(~0u, mx, o));
        float e0 = expf(v0 - mx), e1 = expf(v1 - mx);
        float su = e0 + e1;
#pragma unroll
        for (int o = 16; o > 0; o >>= 1) su += __shfl_xor_sync(~0u, su, o);
        float sc = (s < s_ln) ? (1.f / su) : 0.f;
        ssc[s * 65 + lane] = e0 * sc;
        ssc[s * 65 + 32 + lane] = e1 * sc;
    }
    __syncthreads();

    if (kb == NS - 1) {
        for (int i = tid; i < 4096; i += 256)
            d_out[i] = ssc[(i >> 6) * 65 + (i & 63)];
    }

    int hcol = tid & 63;
    int qgrp = tid >> 6;
#pragma unroll
    for (int pass = 0; pass < 2; pass++) {
        int qb = qgrp * 8 + pass * 32;
        float hc[8][8];
#pragma unroll
        for (int qi = 0; qi < 8; qi++)
#pragma unroll
            for (int hj = 0; hj < 8; hj++) hc[qi][hj] = 0.f;
        for (int s = 0; s < 64; s++) {
            float4 f0 = *(const float4*)(FS + s * 512 + hcol * 8);
            float4 f1 = *(const float4*)(FS + s * 512 + hcol * 8 + 4);
#pragma unroll
            for (int qi = 0; qi < 8; qi++) {
                float a = ssc[s * 65 + qb + qi];
                hc[qi][0] += a * f0.x; hc[qi][1] += a * f0.y;
                hc[qi][2] += a * f0.z; hc[qi][3] += a * f0.w;
                hc[qi][4] += a * f1.x; hc[qi][5] += a * f1.y;
                hc[qi][6] += a * f1.z; hc[qi][7] += a * f1.w;
            }
        }
#pragma unroll
        for (int qi = 0; qi < 8; qi++) {
            float* dst = shc + (qb + qi) * 520 + hcol * 8;
#pragma unroll
            for (int hj = 0; hj < 8; hj++) dst[hj] = hc[qi][hj];
        }
    }
    __syncthreads();

    for (int qi = 0; qi < 8; qi++) {
        int q = warp + qi * 8;
        float dot = 0.f, nq = 0.f, nh = 0.f, ee = 0.f;
        for (int c = 0; c < 16; c++) {
            int h = lane + c * 32;
            float fq = FQ[q * 512 + h];
            float hv = shc[q * 520 + h];
            dot += fq * hv; nq += fq * fq; nh += hv * hv;
            float dd = fq - hv; ee += dd * dd;
        }
#pragma unroll
        for (int o = 16; o > 0; o >>= 1) {
            dot += __shfl_xor_sync(~0u, dot, o);
            nq  += __shfl_xor_sync(~0u, nq,  o);
            nh  += __shfl_xor_sync(~0u, nh,  o);
            ee  += __shfl_xor_sync(~0u, ee,  o);
        }
        if (lane == 0) {
            float cosv = dot / fmaxf(sqrtf(nq) * sqrtf(nh), 1e-6f);
            float eucv = sqrtf(ee);
            float msk = (q < q_ln) ? 1.f : 0.f;
            g_diff[((size_t)kb * 64 + q) * 2 + 0] = cosv * msk;
            g_diff[((size_t)kb * 64 + q) * 2 + 1] = eucv * msk;
        }
    }
}

// ---------------- dml GRU over diff + FC head: 40 blocks x 4 sequences ----------------
__global__ void __launch_bounds__(256) dml_kernel(
    const float* __restrict__ Wih, const float* __restrict__ Whh,
    const float* __restrict__ bih, const float* __restrict__ bhh,
    const float* __restrict__ fcW, const float* __restrict__ fcb,
    float* __restrict__ d_out)
{
    __shared__ __align__(16) float sh[4][256];
    __shared__ float red[256];
    int tid = threadIdx.x;
    int nb = blockIdx.x * 4;

#pragma unroll
    for (int s = 0; s < 4; s++) sh[s][tid] = 0.f;
    __syncthreads();

    float wi_r0 = Wih[tid * 2],         wi_r1 = Wih[tid * 2 + 1];
    float wi_z0 = Wih[(256 + tid) * 2], wi_z1 = Wih[(256 + tid) * 2 + 1];
    float wi_n0 = Wih[(512 + tid) * 2], wi_n1 = Wih[(512 + tid) * 2 + 1];
    float bi_r = bih[tid], bi_z = bih[256 + tid], bi_n = bih[512 + tid];
    float bh_r = bhh[tid], bh_z = bhh[256 + tid], bh_n = bhh[512 + tid];
    const float* wr = Whh + (size_t)tid * 256;
    const float* wz = Whh + (size_t)(256 + tid) * 256;
    const float* wn = Whh + (size_t)(512 + tid) * 256;

    for (int t = 0; t < 64; t++) {
        uint64_t ar[4] = {0,0,0,0}, az[4] = {0,0,0,0}, an[4] = {0,0,0,0};
        for (int i = 0; i < 256; i += 4) {
            ulonglong2 r2 = *(const ulonglong2*)(wr + i);
            ulonglong2 z2 = *(const ulonglong2*)(wz + i);
            ulonglong2 n2 = *(const ulonglong2*)(wn + i);
#pragma unroll
            for (int s = 0; s < 4; s++) {
                ulonglong2 h2 = *(const ulonglong2*)(&sh[s][i]);
                ffma2(ar[s], r2.x, h2.x); ffma2(ar[s], r2.y, h2.y);
                ffma2(az[s], z2.x, h2.x); ffma2(az[s], z2.y, h2.y);
                ffma2(an[s], n2.x, h2.x); ffma2(an[s], n2.y, h2.y);
            }
        }
        float hn[4];
#pragma unroll
        for (int s = 0; s < 4; s++) {
            int n = nb + s;
            float d0 = g_diff[((size_t)n * 64 + t) * 2 + 0];
            float d1 = g_diff[((size_t)n * 64 + t) * 2 + 1];
            float xr = wi_r0 * d0 + wi_r1 * d1 + bi_r;
            float xz = wi_z0 * d0 + wi_z1 * d1 + bi_z;
            float xn = wi_n0 * d0 + wi_n1 * d1 + bi_n;
            float r  = sigm(xr + upk_sum(ar[s]) + bh_r);
            float z  = sigm(xz + upk_sum(az[s]) + bh_z);
            float ng = tanhf(xn + r * (upk_sum(an[s]) + bh_n));
            hn[s] = (1.f - z) * ng + z * sh[s][tid];
        }
        __syncthreads();
#pragma unroll
        for (int s = 0; s < 4; s++) sh[s][tid] = hn[s];
        __syncthreads();
    }

    float fw = fcW[tid];
    for (int s = 0; s < 4; s++) {
        int n = nb + s;
        red[tid] = fw * sh[s][tid];
        __syncthreads();
        for (int off = 128; off > 0; off >>= 1) {
            if (tid < off) red[tid] += red[tid + off];
            __syncthreads();
        }
        if (tid == 0)
            d_out[4096 + n] = sigm(red[0] + fcb[0]);
        __syncthreads();
    }
}

// ---------------- launcher ----------------
extern "C" void kernel_launch(void* const* d_in, const int* in_sizes, int n_in,
                              void* d_out, int out_size)
{
    const float* feats_S  = (const float*)d_in[0];
    const float* feats_Q  = (const float*)d_in[1];
    const float* Wih_f    = (const float*)d_in[2];
    const float* Whh_f    = (const float*)d_in[3];
    const float* bih_f    = (const float*)d_in[4];
    const float* bhh_f    = (const float*)d_in[5];
    const float* Wih_b    = (const float*)d_in[6];
    const float* Whh_b    = (const float*)d_in[7];
    const float* bih_b    = (const float*)d_in[8];
    const float* bhh_b    = (const float*)d_in[9];
    const float* W_attn   = (const float*)d_in[10];
    const float* attn_b   = (const float*)d_in[11];
    const float* dml_Wih  = (const float*)d_in[12];
    const float* dml_Whh  = (const float*)d_in[13];
    const float* dml_bih  = (const float*)d_in[14];
    const float* dml_bhh  = (const float*)d_in[15];
    const float* fc_W     = (const float*)d_in[16];
    const float* fc_b     = (const float*)d_in[17];
    const int*   s_ln     = (const int*)d_in[18];
    const int*   q_ln     = (const int*)d_in[19];
    float* out = (float*)d_out;

    __nv_bfloat16 *abf, *bbf;
    cudaGetSymbolAddress((void**)&abf, g_Abf);
    cudaGetSymbolAddress((void**)&bbf, g_Bbf);

    // 0) fp32 -> bf16 hi/lo split (3 launches, so gemm_mma lands at ncu-captured slot #4)
    convert_split<<<40960, 256>>>(feats_S, abf, abf + AELEMS);
    convert_split<<<8192, 256>>>(feats_Q, abf + (size_t)10240 * DIN,
                                 abf + AELEMS + (size_t)10240 * DIN);
    convert_w<<<6144, 256>>>(Wih_f, Wih_b, bbf, bbf + BELEMS);

    // 1) input projections via bf16 mma.sync, split folded into K'
    cudaFuncSetAttribute(gemm_mma, cudaFuncAttributeMaxDynamicSharedMemorySize, GMM_SMEM);
    gemm_mma<<<dim3(12, 96), 256, GMM_SMEM>>>(bih_f, bih_b);

    // 2) GRU recurrence: 24 seq-groups x 2 directions
    bigru_scan<<<96, 256>>>(Whh_f, bhh_f, Whh_b, bhh_b);

    // 3) keys = W_attn(F_S) + bias : [10240,512] x [512,512]
    gemm_keys<<<dim3(80, 4), 256>>>(W_attn, attn_b, 10240, 512, 512);

    // 4) scores -> softmax -> A -> Hc -> (cos,euc)
    cudaFuncSetAttribute(attn_kernel, cudaFuncAttributeMaxDynamicSharedMemorySize, ATTN_SMEM);
    attn_kernel<<<160, 256, ATTN_SMEM>>>(s_ln, q_ln, out);

    // 5) dml GRU over (cos,euc) + sigmoid(FC)
    dml_kernel<<<40, 256>>>(dml_Wih, dml_Whh, dml_bih, dml_bhh, fc_W, fc_b, out);
}